// round 3
// baseline (speedup 1.0000x reference)
#include <cuda_runtime.h>
#include <math.h>

#define T_SEQ 2048
#define DIM_   1024
#define NH     8
#define HD     128
#define ATTN_SCALE 0.12f
#define RMS_EPS 1.1920929e-7f
#define LOG2E 1.4426950408889634f

// -------------------- scratch (static device globals; no allocs) --------------------
__device__ float g_qkv[(size_t)T_SEQ * 3 * DIM_];   // [t][3072]
__device__ float g_q  [(size_t)NH * T_SEQ * HD];    // [h][t][c]  (tf32-rounded)
__device__ float g_k  [(size_t)NH * T_SEQ * HD];
__device__ float g_v  [(size_t)NH * T_SEQ * HD];
__device__ float g_y  [(size_t)T_SEQ * DIM_];       // [t][h*128+c]

// -------------------- tf32 helpers ---------------------------------------------------
__device__ __forceinline__ unsigned f2tf(float f) {
    unsigned u;
    asm("cvt.rna.tf32.f32 %0, %1;" : "=r"(u) : "f"(f));
    return u;
}

__device__ __forceinline__ void mma_tf32(float c[4], const unsigned a[4], const unsigned b[2]) {
    asm volatile(
        "mma.sync.aligned.m16n8k8.row.col.f32.tf32.tf32.f32 "
        "{%0,%1,%2,%3}, {%4,%5,%6,%7}, {%8,%9}, {%0,%1,%2,%3};"
        : "+f"(c[0]), "+f"(c[1]), "+f"(c[2]), "+f"(c[3])
        : "r"(a[0]), "r"(a[1]), "r"(a[2]), "r"(a[3]), "r"(b[0]), "r"(b[1]));
}

// -------------------- GEMM (tensor core): C[M,N] = A[M,K] @ B[N,K]^T -----------------
// 128x128 block tile, BK=32, 256 threads (8 warps, 2m x 4n), warp tile 64x32.
// SMEM row stride 40 floats: fragment LDS banks = (8*row + k) % 32 -> conflict-free.
__global__ __launch_bounds__(256)
void gemm_nt_tc(const float* __restrict__ A, const float* __restrict__ B,
                float* __restrict__ C, int M, int N, int K)
{
    __shared__ unsigned As[128 * 40];
    __shared__ unsigned Bs[128 * 40];

    const int tid  = threadIdx.x;
    const int lane = tid & 31;
    const int wid  = tid >> 5;
    const int wm   = wid >> 2;   // 0..1 : 64 rows
    const int wn   = wid & 3;    // 0..3 : 32 cols
    const int m0   = blockIdx.y * 128;
    const int n0   = blockIdx.x * 128;

    float acc[4][4][4];
#pragma unroll
    for (int i = 0; i < 4; i++)
#pragma unroll
        for (int j = 0; j < 4; j++)
#pragma unroll
            for (int r = 0; r < 4; r++) acc[i][j][r] = 0.0f;

    for (int k0 = 0; k0 < K; k0 += 32) {
#pragma unroll
        for (int p = 0; p < 4; p++) {
            int f   = tid + p * 256;       // 0..1023
            int row = f >> 3;              // 0..127
            int kq  = (f & 7) << 2;        // 0..28
            float4 va = *(const float4*)(A + (size_t)(m0 + row) * K + k0 + kq);
            uint4 ua = make_uint4(f2tf(va.x), f2tf(va.y), f2tf(va.z), f2tf(va.w));
            *(uint4*)&As[row * 40 + kq] = ua;
            float4 vb = *(const float4*)(B + (size_t)(n0 + row) * K + k0 + kq);
            uint4 ub = make_uint4(f2tf(vb.x), f2tf(vb.y), f2tf(vb.z), f2tf(vb.w));
            *(uint4*)&Bs[row * 40 + kq] = ub;
        }
        __syncthreads();

#pragma unroll
        for (int ks = 0; ks < 4; ks++) {
            const int kk = ks * 8 + (lane & 3);
            unsigned a[4][4];
#pragma unroll
            for (int i = 0; i < 4; i++) {
                int r = wm * 64 + i * 16 + (lane >> 2);
                a[i][0] = As[r * 40 + kk];
                a[i][1] = As[(r + 8) * 40 + kk];
                a[i][2] = As[r * 40 + kk + 4];
                a[i][3] = As[(r + 8) * 40 + kk + 4];
            }
#pragma unroll
            for (int j = 0; j < 4; j++) {
                int n = wn * 32 + j * 8 + (lane >> 2);
                unsigned b[2];
                b[0] = Bs[n * 40 + kk];
                b[1] = Bs[n * 40 + kk + 4];
#pragma unroll
                for (int i = 0; i < 4; i++) mma_tf32(acc[i][j], a[i], b);
            }
        }
        __syncthreads();
    }

#pragma unroll
    for (int i = 0; i < 4; i++) {
        int row0 = m0 + wm * 64 + i * 16 + (lane >> 2);
#pragma unroll
        for (int j = 0; j < 4; j++) {
            int col = n0 + wn * 32 + j * 8 + 2 * (lane & 3);
            *(float2*)&C[(size_t)row0 * N + col]       = make_float2(acc[i][j][0], acc[i][j][1]);
            *(float2*)&C[(size_t)(row0 + 8) * N + col] = make_float2(acc[i][j][2], acc[i][j][3]);
        }
    }
}

// -------------------- transform: rmsnorm + rotary (q,k), lambda mix (v) -------------
__global__ __launch_bounds__(128)
void transform_kernel(const float* __restrict__ ve,
                      const float* __restrict__ lambdas)
{
    const int t = blockIdx.x;
    const int h = blockIdx.y;
    const int c = threadIdx.x;
    const int lane = c & 31;
    const int wid  = c >> 5;

    const float* base = g_qkv + (size_t)t * (3 * DIM_);
    float qv = base[            h * HD + c];
    float kv = base[DIM_      + h * HD + c];
    float vv = base[2 * DIM_  + h * HD + c];

    float sq = qv * qv;
    float sk = kv * kv;
#pragma unroll
    for (int off = 16; off >= 1; off >>= 1) {
        sq += __shfl_xor_sync(0xffffffffu, sq, off);
        sk += __shfl_xor_sync(0xffffffffu, sk, off);
    }
    __shared__ float wq[4], wk[4];
    __shared__ float rq, rk;
    __shared__ float qn[128], kn[128];
    if (lane == 0) { wq[wid] = sq; wk[wid] = sk; }
    __syncthreads();
    if (c == 0) {
        float s1 = wq[0] + wq[1] + wq[2] + wq[3];
        float s2 = wk[0] + wk[1] + wk[2] + wk[3];
        rq = rsqrtf(s1 * (1.0f / 128.0f) + RMS_EPS);
        rk = rsqrtf(s2 * (1.0f / 128.0f) + RMS_EPS);
    }
    __syncthreads();
    qn[c] = qv * rq;
    kn[c] = kv * rk;
    __syncthreads();

    int j = c & 63;
    float cosv, sinv;
    if (j < 32) {
        float tj = (float)j / 31.0f;
        float fr = (float)exp2(-10.0 * (double)tj);
        float th = (float)t * fr;
        cosv = (float)cos((double)th);
        sinv = (float)sin((double)th);
    } else {
        cosv = 1.0f; sinv = 0.0f;
    }

    float qo, ko;
    if (c < 64) {
        qo =  qn[c] * cosv + qn[c + 64] * sinv;
        ko =  kn[c] * cosv + kn[c + 64] * sinv;
    } else {
        qo = -qn[c - 64] * sinv + qn[c] * cosv;
        ko = -kn[c - 64] * sinv + kn[c] * cosv;
    }

    size_t oidx = ((size_t)h * T_SEQ + t) * HD + c;
    // store tf32-rounded values so attention tiles need no conversion
    g_q[oidx] = __uint_as_float(f2tf(qo));
    g_k[oidx] = __uint_as_float(f2tf(ko));

    float vev = ve[(size_t)t * DIM_ + h * HD + c];
    g_v[oidx] = __uint_as_float(f2tf(lambdas[0] * vv + lambdas[1] * vev));
}

// -------------------- flash attention (tensor core, causal) -------------------------
// BM=64 q-rows per block, BN=64 s per tile. 256 threads = 8 warps:
//   wm = wid>>1 (16 rows each), wn = wid&1 (S: 32 cols / O: 64 cols each).
// SMEM strides chosen for conflict-free fragment LDS:
//   Q,K: 132 (%32==4 -> 4r+k), V: 136 (%32==8 -> 8s+d), P: 68 (%32==4).
#define QS_OFF 0
#define KS_OFF (64 * 132)
#define VS_OFF (KS_OFF + 64 * 132)
#define PS_OFF (VS_OFF + 64 * 136)
#define MR_OFF (PS_OFF + 64 * 68)     // mred: 2*64 floats
#define SR_OFF (MR_OFF + 128)         // sred: 2*64 floats
#define ATT_SMEM_WORDS (SR_OFF + 128)

__global__ __launch_bounds__(256)
void attn_tc()
{
    extern __shared__ unsigned sm[];
    unsigned* Qs = sm + QS_OFF;
    unsigned* Ks = sm + KS_OFF;
    unsigned* Vs = sm + VS_OFF;
    unsigned* Ps = sm + PS_OFF;
    float* mred = (float*)(sm + MR_OFF);
    float* sred = (float*)(sm + SR_OFF);

    const int tid  = threadIdx.x;
    const int lane = tid & 31;
    const int wid  = tid >> 5;
    const int wm   = wid >> 1;   // 0..3
    const int wn   = wid & 1;    // 0..1

    const int bid = blockIdx.x;
    const int h   = bid & 7;
    const int qt  = (T_SEQ / 64 - 1) - (bid >> 3);  // heavy tiles scheduled first
    const int q0  = qt * 64;

    const unsigned* qh = (const unsigned*)g_q + (size_t)h * T_SEQ * HD;
    const unsigned* kh = (const unsigned*)g_k + (size_t)h * T_SEQ * HD;
    const unsigned* vh = (const unsigned*)g_v + (size_t)h * T_SEQ * HD;

    // load Q tile [64][128] (row stride 132)
#pragma unroll
    for (int p = 0; p < 8; p++) {
        int f   = tid + p * 256;
        int row = f >> 5;
        int c   = (f & 31) << 2;
        uint4 v = *(const uint4*)&qh[(size_t)(q0 + row) * HD + c];
        *(uint4*)&Qs[row * 132 + c] = v;
    }

    const int lr0 = wm * 16 + (lane >> 2);   // local row
    const int lr1 = lr0 + 8;

    float m_i[2] = {-INFINITY, -INFINITY};
    float l_i[2] = {0.0f, 0.0f};
    float O[8][4];
#pragma unroll
    for (int nf = 0; nf < 8; nf++)
#pragma unroll
        for (int r = 0; r < 4; r++) O[nf][r] = 0.0f;

    for (int t = 0; t <= qt; t++) {
        const int s0 = t * 64;
        __syncthreads();   // previous PV done with Ks/Vs (and Qs load on t=0)

#pragma unroll
        for (int p = 0; p < 8; p++) {
            int f   = tid + p * 256;
            int row = f >> 5;
            int c   = (f & 31) << 2;
            uint4 vk = *(const uint4*)&kh[(size_t)(s0 + row) * HD + c];
            *(uint4*)&Ks[row * 132 + c] = vk;
            uint4 vv = *(const uint4*)&vh[(size_t)(s0 + row) * HD + c];
            *(uint4*)&Vs[row * 136 + c] = vv;
        }
        __syncthreads();

        // ---- S = Q K^T (warp: rows wm*16..+16, cols wn*32..+32) ----
        float sacc[4][4];
#pragma unroll
        for (int j = 0; j < 4; j++)
#pragma unroll
            for (int r = 0; r < 4; r++) sacc[j][r] = 0.0f;

#pragma unroll
        for (int ks = 0; ks < 16; ks++) {
            const int kk = ks * 8 + (lane & 3);
            unsigned a[4];
            a[0] = Qs[lr0 * 132 + kk];
            a[1] = Qs[lr1 * 132 + kk];
            a[2] = Qs[lr0 * 132 + kk + 4];
            a[3] = Qs[lr1 * 132 + kk + 4];
#pragma unroll
            for (int j = 0; j < 4; j++) {
                int n = wn * 32 + j * 8 + (lane >> 2);
                unsigned b[2];
                b[0] = Ks[n * 132 + kk];
                b[1] = Ks[n * 132 + kk + 4];
                mma_tf32(sacc[j], a, b);
            }
        }

        // scale + causal mask
        const bool diag = (s0 == q0);
        const int gr0 = q0 + lr0, gr1 = q0 + lr1;
#pragma unroll
        for (int j = 0; j < 4; j++) {
            int c0 = s0 + wn * 32 + j * 8 + 2 * (lane & 3);
            float v0 = sacc[j][0] * ATTN_SCALE;
            float v1 = sacc[j][1] * ATTN_SCALE;
            float v2 = sacc[j][2] * ATTN_SCALE;
            float v3 = sacc[j][3] * ATTN_SCALE;
            if (diag) {
                if (c0     > gr0) v0 = -INFINITY;
                if (c0 + 1 > gr0) v1 = -INFINITY;
                if (c0     > gr1) v2 = -INFINITY;
                if (c0 + 1 > gr1) v3 = -INFINITY;
            }
            sacc[j][0] = v0; sacc[j][1] = v1; sacc[j][2] = v2; sacc[j][3] = v3;
        }

        // ---- row max (quad reduce, then cross-warp via SMEM) ----
        float mx0 = fmaxf(fmaxf(sacc[0][0], sacc[0][1]), fmaxf(sacc[1][0], sacc[1][1]));
        mx0 = fmaxf(mx0, fmaxf(fmaxf(sacc[2][0], sacc[2][1]), fmaxf(sacc[3][0], sacc[3][1])));
        float mx1 = fmaxf(fmaxf(sacc[0][2], sacc[0][3]), fmaxf(sacc[1][2], sacc[1][3]));
        mx1 = fmaxf(mx1, fmaxf(fmaxf(sacc[2][2], sacc[2][3]), fmaxf(sacc[3][2], sacc[3][3])));
#pragma unroll
        for (int off = 1; off <= 2; off <<= 1) {
            mx0 = fmaxf(mx0, __shfl_xor_sync(0xffffffffu, mx0, off));
            mx1 = fmaxf(mx1, __shfl_xor_sync(0xffffffffu, mx1, off));
        }
        if ((lane & 3) == 0) {
            mred[wn * 64 + lr0] = mx0;
            mred[wn * 64 + lr1] = mx1;
        }
        __syncthreads();
        float mn0 = fmaxf(m_i[0], fmaxf(mred[lr0], mred[64 + lr0]));
        float mn1 = fmaxf(m_i[1], fmaxf(mred[lr1], mred[64 + lr1]));

        // ---- exp + P store + row sum ----
        float rs0 = 0.0f, rs1 = 0.0f;
#pragma unroll
        for (int j = 0; j < 4; j++) {
            int col = wn * 32 + j * 8 + 2 * (lane & 3);
            float p00 = exp2f((sacc[j][0] - mn0) * LOG2E);
            float p01 = exp2f((sacc[j][1] - mn0) * LOG2E);
            float p10 = exp2f((sacc[j][2] - mn1) * LOG2E);
            float p11 = exp2f((sacc[j][3] - mn1) * LOG2E);
            rs0 += p00 + p01;
            rs1 += p10 + p11;
            *(uint2*)&Ps[lr0 * 68 + col] = make_uint2(f2tf(p00), f2tf(p01));
            *(uint2*)&Ps[lr1 * 68 + col] = make_uint2(f2tf(p10), f2tf(p11));
        }
#pragma unroll
        for (int off = 1; off <= 2; off <<= 1) {
            rs0 += __shfl_xor_sync(0xffffffffu, rs0, off);
            rs1 += __shfl_xor_sync(0xffffffffu, rs1, off);
        }
        if ((lane & 3) == 0) {
            sred[wn * 64 + lr0] = rs0;
            sred[wn * 64 + lr1] = rs1;
        }
        __syncthreads();
        float tot0 = sred[lr0] + sred[64 + lr0];
        float tot1 = sred[lr1] + sred[64 + lr1];

        float al0 = exp2f((m_i[0] - mn0) * LOG2E);   // 0 on first tile
        float al1 = exp2f((m_i[1] - mn1) * LOG2E);
        l_i[0] = l_i[0] * al0 + tot0;  m_i[0] = mn0;
        l_i[1] = l_i[1] * al1 + tot1;  m_i[1] = mn1;
#pragma unroll
        for (int nf = 0; nf < 8; nf++) {
            O[nf][0] *= al0; O[nf][1] *= al0;
            O[nf][2] *= al1; O[nf][3] *= al1;
        }

        // ---- O += P @ V (warp: rows wm*16..+16, cols wn*64..+64) ----
#pragma unroll
        for (int ks = 0; ks < 8; ks++) {
            const int kk = ks * 8 + (lane & 3);
            unsigned a[4];
            a[0] = Ps[lr0 * 68 + kk];
            a[1] = Ps[lr1 * 68 + kk];
            a[2] = Ps[lr0 * 68 + kk + 4];
            a[3] = Ps[lr1 * 68 + kk + 4];
#pragma unroll
            for (int nf = 0; nf < 8; nf++) {
                int n = wn * 64 + nf * 8 + (lane >> 2);
                unsigned b[2];
                b[0] = Vs[kk * 136 + n];
                b[1] = Vs[(kk + 4) * 136 + n];
                mma_tf32(O[nf], a, b);
            }
        }
    }

    // epilogue
    float inv0 = 1.0f / l_i[0];
    float inv1 = 1.0f / l_i[1];
    const int row0 = q0 + lr0, row1 = q0 + lr1;
#pragma unroll
    for (int nf = 0; nf < 8; nf++) {
        int col = h * HD + wn * 64 + nf * 8 + 2 * (lane & 3);
        *(float2*)&g_y[(size_t)row0 * DIM_ + col] = make_float2(O[nf][0] * inv0, O[nf][1] * inv0);
        *(float2*)&g_y[(size_t)row1 * DIM_ + col] = make_float2(O[nf][2] * inv1, O[nf][3] * inv1);
    }
}

// -------------------- launch ---------------------------------------------------------
extern "C" void kernel_launch(void* const* d_in, const int* in_sizes, int n_in,
                              void* d_out, int out_size)
{
    const float* x        = (const float*)d_in[0];
    const float* ve       = (const float*)d_in[1];
    const float* qkv_w    = (const float*)d_in[2];
    const float* lambdas  = (const float*)d_in[3];
    const float* c_proj_w = (const float*)d_in[4];
    float* out = (float*)d_out;

    float *p_qkv, *p_y;
    cudaGetSymbolAddress((void**)&p_qkv, g_qkv);
    cudaGetSymbolAddress((void**)&p_y,   g_y);

    // 1) QKV projection: g_qkv[2048,3072] = x[2048,1024] @ qkv_w^T
    gemm_nt_tc<<<dim3(3 * DIM_ / 128, T_SEQ / 128), 256>>>(x, qkv_w, p_qkv, T_SEQ, 3 * DIM_, DIM_);

    // 2) rmsnorm + rotary + v mix (outputs tf32-rounded)
    transform_kernel<<<dim3(T_SEQ, NH), 128>>>(ve, lambdas);

    // 3) causal flash attention (tensor core)
    cudaFuncSetAttribute(attn_tc, cudaFuncAttributeMaxDynamicSharedMemorySize,
                         ATT_SMEM_WORDS * (int)sizeof(unsigned));
    attn_tc<<<dim3((T_SEQ / 64) * NH), 256, ATT_SMEM_WORDS * sizeof(unsigned)>>>();

    // 4) output projection: out[2048,1024] = g_y @ c_proj_w^T
    gemm_nt_tc<<<dim3(DIM_ / 128, T_SEQ / 128), 256>>>(p_y, c_proj_w, out, T_SEQ, DIM_, DIM_);
}

// round 6
// speedup vs baseline: 1.5979x; 1.5979x over previous
#include <cuda_runtime.h>
#include <cuda_fp16.h>
#include <math.h>

#define T_SEQ 2048
#define DIM_   1024
#define NH     8
#define HD     128
#define RMS_EPS 1.1920929e-7f
#define C_SC (0.12f * 1.4426950408889634f)   // ATTN_SCALE * log2(e)

// -------------------- scratch (static device globals; no allocs) --------------------
__device__ float  g_qkv[(size_t)T_SEQ * 3 * DIM_];   // [t][3072] fp32
__device__ __half g_qh [(size_t)NH * T_SEQ * HD];    // [h][t][d]
__device__ __half g_kh [(size_t)NH * T_SEQ * HD];    // [h][t][d]
__device__ __half g_vt [(size_t)NH * HD * T_SEQ];    // [h][d][t]  transposed V
__device__ float  g_y  [(size_t)T_SEQ * DIM_];       // [t][h*128+d]

// -------------------- helpers --------------------------------------------------------
__device__ __forceinline__ uint2 f4h(float4 v) {
    uint2 r;
    asm("cvt.rn.f16x2.f32 %0, %1, %2;" : "=r"(r.x) : "f"(v.y), "f"(v.x));
    asm("cvt.rn.f16x2.f32 %0, %1, %2;" : "=r"(r.y) : "f"(v.w), "f"(v.z));
    return r;
}
__device__ __forceinline__ unsigned packh2(float lo, float hi) {
    unsigned r;
    asm("cvt.rn.f16x2.f32 %0, %1, %2;" : "=r"(r) : "f"(hi), "f"(lo));
    return r;
}
__device__ __forceinline__ void mma_h(float c[4], const unsigned a[4], const unsigned* b) {
    asm volatile(
        "mma.sync.aligned.m16n8k16.row.col.f32.f16.f16.f32 "
        "{%0,%1,%2,%3}, {%4,%5,%6,%7}, {%8,%9}, {%0,%1,%2,%3};"
        : "+f"(c[0]), "+f"(c[1]), "+f"(c[2]), "+f"(c[3])
        : "r"(a[0]), "r"(a[1]), "r"(a[2]), "r"(a[3]), "r"(b[0]), "r"(b[1]));
}
__device__ __forceinline__ void ldm4(unsigned r[4], unsigned addr) {
    asm volatile("ldmatrix.sync.aligned.m8n8.x4.shared.b16 {%0,%1,%2,%3}, [%4];"
                 : "=r"(r[0]), "=r"(r[1]), "=r"(r[2]), "=r"(r[3]) : "r"(addr));
}
__device__ __forceinline__ unsigned smem_u32(const void* p) {
    unsigned a;
    asm("{.reg .u64 t; cvta.to.shared.u64 t, %1; cvt.u32.u64 %0, t;}" : "=r"(a) : "l"(p));
    return a;
}
__device__ __forceinline__ void cpa16(unsigned dst, const void* src) {
    asm volatile("cp.async.cg.shared.global [%0], [%1], 16;" :: "r"(dst), "l"(src) : "memory");
}
__device__ __forceinline__ void cp_commit() { asm volatile("cp.async.commit_group;" ::: "memory"); }
__device__ __forceinline__ void cp_wait1()  { asm volatile("cp.async.wait_group 1;" ::: "memory"); }
__device__ __forceinline__ void cp_wait0()  { asm volatile("cp.async.wait_group 0;" ::: "memory"); }

// -------------------- GEMM (fp16 TC): C[M,N] = A[M,K] @ B[N,K]^T ---------------------
// BM=64, BN=128, BK=32, 256 threads = 8 warps (2m x 4n), warp tile 32x32.
// SMEM rows padded to 20 u32 (40 halfs): conflict-free ldmatrix.
__global__ __launch_bounds__(256)
void gemm_h(const float* __restrict__ A, const float* __restrict__ B,
            float* __restrict__ C, int M, int N, int K)
{
    __shared__ unsigned As[2][64 * 20];
    __shared__ unsigned Bs[2][128 * 20];

    const int tid  = threadIdx.x;
    const int lane = tid & 31;
    const int wid  = tid >> 5;
    const int wm   = wid >> 2;   // 0..1
    const int wn   = wid & 3;    // 0..3
    const int m0   = blockIdx.y * 64;
    const int n0   = blockIdx.x * 128;

    // ldmatrix per-thread address components
    const int arow = (lane & 7) + ((lane >> 3) & 1) * 8;   // A: m0 row within 16
    const int acol = (lane >> 4) * 4;                      // A: k-half select (u32)
    const int brow = (lane & 7) + ((lane >> 4) & 1) * 8;   // B: n row within 16 (j-pair)
    const int bcol = ((lane >> 3) & 1) * 4;                // B: b0/b1 select

    const unsigned as_b = smem_u32(As);
    const unsigned bs_b = smem_u32(Bs);

    float acc[2][4][4];
#pragma unroll
    for (int i = 0; i < 2; i++)
#pragma unroll
        for (int j = 0; j < 4; j++)
#pragma unroll
            for (int r = 0; r < 4; r++) acc[i][j][r] = 0.0f;

    float4 ra[2], rb[4];
    const int NK = K >> 5;

    // prologue load
    {
        int kb = 0;
#pragma unroll
        for (int p = 0; p < 2; p++) {
            int f = tid + p * 256;
            ra[p] = *(const float4*)(A + (size_t)(m0 + (f >> 3)) * K + kb + (f & 7) * 4);
        }
#pragma unroll
        for (int p = 0; p < 4; p++) {
            int f = tid + p * 256;
            rb[p] = *(const float4*)(B + (size_t)(n0 + (f >> 3)) * K + kb + (f & 7) * 4);
        }
#pragma unroll
        for (int p = 0; p < 2; p++) {
            int f = tid + p * 256;
            *(uint2*)&As[0][(f >> 3) * 20 + (f & 7) * 2] = f4h(ra[p]);
        }
#pragma unroll
        for (int p = 0; p < 4; p++) {
            int f = tid + p * 256;
            *(uint2*)&Bs[0][(f >> 3) * 20 + (f & 7) * 2] = f4h(rb[p]);
        }
    }
    __syncthreads();

    for (int it = 0; it < NK; it++) {
        const int b = it & 1;
        if (it + 1 < NK) {
            int kb = (it + 1) * 32;
#pragma unroll
            for (int p = 0; p < 2; p++) {
                int f = tid + p * 256;
                ra[p] = *(const float4*)(A + (size_t)(m0 + (f >> 3)) * K + kb + (f & 7) * 4);
            }
#pragma unroll
            for (int p = 0; p < 4; p++) {
                int f = tid + p * 256;
                rb[p] = *(const float4*)(B + (size_t)(n0 + (f >> 3)) * K + kb + (f & 7) * 4);
            }
        }

        const unsigned ab = as_b + b * (64 * 20 * 4);
        const unsigned bb = bs_b + b * (128 * 20 * 4);
#pragma unroll
        for (int ks = 0; ks < 2; ks++) {
            unsigned a[2][4], bq[2][4];
#pragma unroll
            for (int mi = 0; mi < 2; mi++)
                ldm4(a[mi], ab + ((wm * 32 + mi * 16 + arow) * 20 + ks * 8 + acol) * 4);
#pragma unroll
            for (int jp = 0; jp < 2; jp++)
                ldm4(bq[jp], bb + ((wn * 32 + jp * 16 + brow) * 20 + ks * 8 + bcol) * 4);
#pragma unroll
            for (int j = 0; j < 4; j++) {
                const unsigned* pb = &bq[j >> 1][(j & 1) * 2];
                mma_h(acc[0][j], a[0], pb);
                mma_h(acc[1][j], a[1], pb);
            }
        }

        if (it + 1 < NK) {
#pragma unroll
            for (int p = 0; p < 2; p++) {
                int f = tid + p * 256;
                *(uint2*)&As[b ^ 1][(f >> 3) * 20 + (f & 7) * 2] = f4h(ra[p]);
            }
#pragma unroll
            for (int p = 0; p < 4; p++) {
                int f = tid + p * 256;
                *(uint2*)&Bs[b ^ 1][(f >> 3) * 20 + (f & 7) * 2] = f4h(rb[p]);
            }
        }
        __syncthreads();
    }

    const int rq = lane >> 2, cq = lane & 3;
#pragma unroll
    for (int mi = 0; mi < 2; mi++) {
        int r = m0 + wm * 32 + mi * 16 + rq;
#pragma unroll
        for (int j = 0; j < 4; j++) {
            int cn = n0 + wn * 32 + j * 8 + 2 * cq;
            *(float2*)&C[(size_t)r * N + cn]       = make_float2(acc[mi][j][0], acc[mi][j][1]);
            *(float2*)&C[(size_t)(r + 8) * N + cn] = make_float2(acc[mi][j][2], acc[mi][j][3]);
        }
    }
}

// -------------------- q/k transform: rmsnorm + rotary -> fp16 ------------------------
__global__ __launch_bounds__(128)
void qk_transform()
{
    const int t = blockIdx.x;
    const int h = blockIdx.y;
    const int c = threadIdx.x;
    const int lane = c & 31;
    const int wid  = c >> 5;

    const float* base = g_qkv + (size_t)t * (3 * DIM_);
    float qv = base[       h * HD + c];
    float kv = base[DIM_ + h * HD + c];

    float sq = qv * qv;
    float sk = kv * kv;
#pragma unroll
    for (int off = 16; off >= 1; off >>= 1) {
        sq += __shfl_xor_sync(0xffffffffu, sq, off);
        sk += __shfl_xor_sync(0xffffffffu, sk, off);
    }
    __shared__ float wq[4], wk[4], rq, rk, qn[128], kn[128];
    if (lane == 0) { wq[wid] = sq; wk[wid] = sk; }
    __syncthreads();
    if (c == 0) {
        rq = rsqrtf((wq[0] + wq[1] + wq[2] + wq[3]) * (1.0f / 128.0f) + RMS_EPS);
        rk = rsqrtf((wk[0] + wk[1] + wk[2] + wk[3]) * (1.0f / 128.0f) + RMS_EPS);
    }
    __syncthreads();
    qn[c] = qv * rq;
    kn[c] = kv * rk;
    __syncthreads();

    int j = c & 63;
    float cosv, sinv;
    if (j < 32) {
        float tj = (float)j / 31.0f;
        float fr = (float)exp2(-10.0 * (double)tj);
        float th = (float)t * fr;
        cosv = (float)cos((double)th);
        sinv = (float)sin((double)th);
    } else {
        cosv = 1.0f; sinv = 0.0f;
    }

    float qo, ko;
    if (c < 64) {
        qo =  qn[c] * cosv + qn[c + 64] * sinv;
        ko =  kn[c] * cosv + kn[c + 64] * sinv;
    } else {
        qo = -qn[c - 64] * sinv + qn[c] * cosv;
        ko = -kn[c - 64] * sinv + kn[c] * cosv;
    }

    size_t oidx = ((size_t)h * T_SEQ + t) * HD + c;
    g_qh[oidx] = __float2half_rn(qo);
    g_kh[oidx] = __float2half_rn(ko);
}

// -------------------- v mix + transpose: g_vt[h][d][t] -------------------------------
__global__ __launch_bounds__(128)
void vmix_trans(const float* __restrict__ ve, const float* __restrict__ lambdas)
{
    __shared__ __half tile[64 * 136];
    const int h  = blockIdx.y;
    const int t0 = blockIdx.x * 64;
    const int tid = threadIdx.x;
    const float l0 = lambdas[0], l1 = lambdas[1];

#pragma unroll
    for (int p = 0; p < 16; p++) {
        int f = tid + p * 128;
        int row = f >> 5, c4 = (f & 31) * 4;
        float4 v = *(const float4*)(g_qkv + (size_t)(t0 + row) * (3 * DIM_) + 2 * DIM_ + h * HD + c4);
        float4 e = *(const float4*)(ve + (size_t)(t0 + row) * DIM_ + h * HD + c4);
        tile[row * 136 + c4 + 0] = __float2half_rn(l0 * v.x + l1 * e.x);
        tile[row * 136 + c4 + 1] = __float2half_rn(l0 * v.y + l1 * e.y);
        tile[row * 136 + c4 + 2] = __float2half_rn(l0 * v.z + l1 * e.z);
        tile[row * 136 + c4 + 3] = __float2half_rn(l0 * v.w + l1 * e.w);
    }
    __syncthreads();

#pragma unroll
    for (int p = 0; p < 8; p++) {
        int f = tid + p * 128;
        int d = f >> 3, s8 = (f & 7) * 8;
        __half tmp[8];
#pragma unroll
        for (int i = 0; i < 8; i++) tmp[i] = tile[(s8 + i) * 136 + d];
        *(uint4*)(g_vt + ((size_t)h * HD + d) * T_SEQ + t0 + s8) = *(uint4*)tmp;
    }
}

// -------------------- flash attention (fp16 TC, causal, balanced pairs) --------------
// 128 blocks, 128 threads (4 warps x 16 q-rows = 64-row q-tile), BN=64.
// Block b: head = b&7, pair index pr = b>>3 -> q-tiles {pr, 31-pr} = 34 k-tiles each.
// SMEM (u32): Qs[0,4352) Ks0[4352) Ks1[8704) Vt0[13056) Vt1[17664) end 22272.
#define ATT_SMEM_BYTES (22272 * 4)

__global__ __launch_bounds__(128)
void attn_h()
{
    extern __shared__ unsigned sm[];
    const int tid  = threadIdx.x;
    const int lane = tid & 31;
    const int w    = tid >> 5;
    const int rq   = lane >> 2;
    const int cq   = lane & 3;
    const int h    = blockIdx.x & 7;
    const int pr   = blockIdx.x >> 3;

    const __half* qh = g_qh + (size_t)h * T_SEQ * HD;
    const __half* kh = g_kh + (size_t)h * T_SEQ * HD;
    const __half* vt = g_vt + (size_t)h * HD * T_SEQ;

    const unsigned smb = smem_u32(sm);
    const int arow = (lane & 7) + ((lane >> 3) & 1) * 8;
    const int acol = (lane >> 4) * 4;
    const int brow = (lane & 7) + ((lane >> 4) & 1) * 8;
    const int bcol = ((lane >> 3) & 1) * 4;

    for (int hi = 0; hi < 2; hi++) {
        const int qt = hi ? (31 - pr) : pr;
        const int q0 = qt * 64;

        __syncthreads();   // SMEM free from previous half

        // prologue: Q (group), KV tile 0 (group)
#pragma unroll
        for (int p = 0; p < 8; p++) {
            int id = tid + p * 128;
            int row = id >> 4, o = id & 15;
            cpa16(smb + row * 272u + o * 16u, qh + (size_t)(q0 + row) * HD + o * 8);
        }
        cp_commit();
        {
#pragma unroll
            for (int p = 0; p < 8; p++) {
                int id = tid + p * 128;
                int row = id >> 4, o = id & 15;
                cpa16(smb + 4352u * 4u + row * 272u + o * 16u, kh + (size_t)row * HD + o * 8);
            }
#pragma unroll
            for (int p = 0; p < 8; p++) {
                int id = tid + p * 128;
                int d = id >> 3, o = id & 7;
                cpa16(smb + 13056u * 4u + d * 144u + o * 16u, vt + (size_t)d * T_SEQ + o * 8);
            }
        }
        cp_commit();
        cp_wait1();        // Q ready
        __syncthreads();

        // Q fragments (warp rows w*16..+16)
        unsigned qa[8][4];
#pragma unroll
        for (int ks = 0; ks < 8; ks++)
            ldm4(qa[ks], smb + ((w * 16 + arow) * 68 + ks * 8 + acol) * 4);

        float m0 = -INFINITY, m1 = -INFINITY, l0 = 0.0f, l1 = 0.0f;
        float O[16][4];
#pragma unroll
        for (int nf = 0; nf < 16; nf++)
#pragma unroll
            for (int r = 0; r < 4; r++) O[nf][r] = 0.0f;

        for (int t = 0; t <= qt; t++) {
            if (t < qt) {
                const int s0 = (t + 1) * 64;
                const int b2 = (t + 1) & 1;
                const unsigned kb = smb + (4352u + b2 * 4352u) * 4u;
                const unsigned vb = smb + (13056u + b2 * 4608u) * 4u;
#pragma unroll
                for (int p = 0; p < 8; p++) {
                    int id = tid + p * 128;
                    int row = id >> 4, o = id & 15;
                    cpa16(kb + row * 272u + o * 16u, kh + (size_t)(s0 + row) * HD + o * 8);
                }
#pragma unroll
                for (int p = 0; p < 8; p++) {
                    int id = tid + p * 128;
                    int d = id >> 3, o = id & 7;
                    cpa16(vb + d * 144u + o * 16u, vt + (size_t)d * T_SEQ + s0 + o * 8);
                }
                cp_commit();
                cp_wait1();
            } else {
                cp_wait0();
            }
            __syncthreads();   // tile t visible; prev buffers free

            const int b = t & 1;
            const unsigned kb = smb + (4352u + b * 4352u) * 4u;
            const unsigned vb = smb + (13056u + b * 4608u) * 4u;

            // ---- S = Q K^T ----
            float s[8][4];
#pragma unroll
            for (int nf = 0; nf < 8; nf++)
#pragma unroll
                for (int r = 0; r < 4; r++) s[nf][r] = 0.0f;

#pragma unroll
            for (int ks = 0; ks < 8; ks++) {
#pragma unroll
                for (int np = 0; np < 4; np++) {
                    unsigned kq[4];
                    ldm4(kq, kb + ((np * 16 + brow) * 68 + ks * 8 + bcol) * 4);
                    mma_h(s[2 * np],     qa[ks], &kq[0]);
                    mma_h(s[2 * np + 1], qa[ks], &kq[2]);
                }
            }

            // scale into log2 domain + causal mask on diagonal tile
            const int r0l = w * 16 + rq, r1l = r0l + 8;
#pragma unroll
            for (int nf = 0; nf < 8; nf++) {
                s[nf][0] *= C_SC; s[nf][1] *= C_SC;
                s[nf][2] *= C_SC; s[nf][3] *= C_SC;
            }
            if (t == qt) {
#pragma unroll
                for (int nf = 0; nf < 8; nf++) {
                    int c0 = nf * 8 + 2 * cq;
                    if (c0     > r0l) s[nf][0] = -INFINITY;
                    if (c0 + 1 > r0l) s[nf][1] = -INFINITY;
                    if (c0     > r1l) s[nf][2] = -INFINITY;
                    if (c0 + 1 > r1l) s[nf][3] = -INFINITY;
                }
            }

            // ---- warp-local row max ----
            float mx0 = -INFINITY, mx1 = -INFINITY;
#pragma unroll
            for (int nf = 0; nf < 8; nf++) {
                mx0 = fmaxf(mx0, fmaxf(s[nf][0], s[nf][1]));
                mx1 = fmaxf(mx1, fmaxf(s[nf][2], s[nf][3]));
            }
#pragma unroll
            for (int off = 1; off <= 2; off <<= 1) {
                mx0 = fmaxf(mx0, __shfl_xor_sync(0xffffffffu, mx0, off));
                mx1 = fmaxf(mx1, __shfl_xor_sync(0xffffffffu, mx1, off));
            }
            const float nm0 = fmaxf(m0, mx0);
            const float nm1 = fmaxf(m1, mx1);

            // ---- exp (base-2), P stays in registers as fp16 A-fragments ----
            float rs0 = 0.0f, rs1 = 0.0f;
            unsigned ph[8][2];
#pragma unroll
            for (int nf = 0; nf < 8; nf++) {
                float p0 = exp2f(s[nf][0] - nm0);
                float p1 = exp2f(s[nf][1] - nm0);
                float p2 = exp2f(s[nf][2] - nm1);
                float p3 = exp2f(s[nf][3] - nm1);
                rs0 += p0 + p1;
                rs1 += p2 + p3;
                ph[nf][0] = packh2(p0, p1);
                ph[nf][1] = packh2(p2, p3);
            }
#pragma unroll
            for (int off = 1; off <= 2; off <<= 1) {
                rs0 += __shfl_xor_sync(0xffffffffu, rs0, off);
                rs1 += __shfl_xor_sync(0xffffffffu, rs1, off);
            }

            const float al0 = exp2f(m0 - nm0);   // 0 on first tile
            const float al1 = exp2f(m1 - nm1);
            l0 = l0 * al0 + rs0;  m0 = nm0;
            l1 = l1 * al1 + rs1;  m1 = nm1;
#pragma unroll
            for (int nf = 0; nf < 16; nf++) {
                O[nf][0] *= al0; O[nf][1] *= al0;
                O[nf][2] *= al1; O[nf][3] *= al1;
            }

            // ---- O += P @ V ----
#pragma unroll
            for (int ks = 0; ks < 4; ks++) {
                unsigned a[4] = { ph[2 * ks][0], ph[2 * ks][1],
                                  ph[2 * ks + 1][0], ph[2 * ks + 1][1] };
#pragma unroll
                for (int np = 0; np < 8; np++) {
                    unsigned vq[4];
                    ldm4(vq, vb + ((np * 16 + brow) * 36 + ks * 8 + bcol) * 4);
                    mma_h(O[2 * np],     a, &vq[0]);
                    mma_h(O[2 * np + 1], a, &vq[2]);
                }
            }
        }

        // epilogue
        const float inv0 = 1.0f / l0;
        const float inv1 = 1.0f / l1;
        const int row0 = q0 + w * 16 + rq, row1 = row0 + 8;
#pragma unroll
        for (int nf = 0; nf < 16; nf++) {
            int col = h * HD + nf * 8 + 2 * cq;
            *(float2*)&g_y[(size_t)row0 * DIM_ + col] = make_float2(O[nf][0] * inv0, O[nf][1] * inv0);
            *(float2*)&g_y[(size_t)row1 * DIM_ + col] = make_float2(O[nf][2] * inv1, O[nf][3] * inv1);
        }
    }
}

// -------------------- launch ---------------------------------------------------------
extern "C" void kernel_launch(void* const* d_in, const int* in_sizes, int n_in,
                              void* d_out, int out_size)
{
    const float* x        = (const float*)d_in[0];
    const float* ve       = (const float*)d_in[1];
    const float* qkv_w    = (const float*)d_in[2];
    const float* lambdas  = (const float*)d_in[3];
    const float* c_proj_w = (const float*)d_in[4];
    float* out = (float*)d_out;

    float *p_qkv, *p_y;
    cudaGetSymbolAddress((void**)&p_qkv, g_qkv);
    cudaGetSymbolAddress((void**)&p_y,   g_y);

    // 1) QKV projection: g_qkv[2048,3072] = x @ qkv_w^T
    gemm_h<<<dim3(3 * DIM_ / 128, T_SEQ / 64), 256>>>(x, qkv_w, p_qkv, T_SEQ, 3 * DIM_, DIM_);

    // 2) rmsnorm + rotary (q,k -> fp16) ; v mix + transpose (fp16)
    qk_transform<<<dim3(T_SEQ, NH), 128>>>();
    vmix_trans<<<dim3(T_SEQ / 64, NH), 128>>>(ve, lambdas);

    // 3) causal flash attention
    cudaFuncSetAttribute(attn_h, cudaFuncAttributeMaxDynamicSharedMemorySize, ATT_SMEM_BYTES);
    attn_h<<<dim3(128), 128, ATT_SMEM_BYTES>>>();

    // 4) output projection: out = g_y @ c_proj_w^T
    gemm_h<<<dim3(DIM_ / 128, T_SEQ / 64), 256>>>(p_y, c_proj_w, out, T_SEQ, DIM_, DIM_);
}

// round 7
// speedup vs baseline: 2.9284x; 1.8327x over previous
#include <cuda_runtime.h>
#include <cuda_fp16.h>
#include <math.h>

#define T_SEQ 2048
#define DIM_   1024
#define NH     8
#define HD     128
#define RMS_EPS 1.1920929e-7f
#define C_SC (0.12f * 1.4426950408889634f)   // ATTN_SCALE * log2(e)

// -------------------- scratch (static device globals; no allocs) --------------------
__device__ float  g_qkv  [(size_t)T_SEQ * 3 * DIM_];  // [t][3072] fp32
__device__ __half g_xh   [(size_t)T_SEQ * DIM_];      // fp16 x
__device__ __half g_wqkv [(size_t)3 * DIM_ * DIM_];   // fp16 qkv_w
__device__ __half g_wproj[(size_t)DIM_ * DIM_];       // fp16 c_proj_w
__device__ __half g_qh   [(size_t)NH * T_SEQ * HD];   // [h][t][d]
__device__ __half g_kh   [(size_t)NH * T_SEQ * HD];   // [h][t][d]
__device__ __half g_vt   [(size_t)NH * HD * T_SEQ];   // [h][d][t]
__device__ __half g_yh   [(size_t)T_SEQ * DIM_];      // attention out, fp16
__device__ float  g_rot  [(size_t)T_SEQ * 64];        // [t][2*j] cos, [t][2*j+1] sin

// -------------------- helpers --------------------------------------------------------
__device__ __forceinline__ uint2 f4h(float4 v) {
    uint2 r;
    asm("cvt.rn.f16x2.f32 %0, %1, %2;" : "=r"(r.x) : "f"(v.y), "f"(v.x));
    asm("cvt.rn.f16x2.f32 %0, %1, %2;" : "=r"(r.y) : "f"(v.w), "f"(v.z));
    return r;
}
__device__ __forceinline__ unsigned packh2(float lo, float hi) {
    unsigned r;
    asm("cvt.rn.f16x2.f32 %0, %1, %2;" : "=r"(r) : "f"(hi), "f"(lo));
    return r;
}
__device__ __forceinline__ void mma_h(float c[4], const unsigned a[4], const unsigned* b) {
    asm volatile(
        "mma.sync.aligned.m16n8k16.row.col.f32.f16.f16.f32 "
        "{%0,%1,%2,%3}, {%4,%5,%6,%7}, {%8,%9}, {%0,%1,%2,%3};"
        : "+f"(c[0]), "+f"(c[1]), "+f"(c[2]), "+f"(c[3])
        : "r"(a[0]), "r"(a[1]), "r"(a[2]), "r"(a[3]), "r"(b[0]), "r"(b[1]));
}
__device__ __forceinline__ void ldm4(unsigned r[4], unsigned addr) {
    asm volatile("ldmatrix.sync.aligned.m8n8.x4.shared.b16 {%0,%1,%2,%3}, [%4];"
                 : "=r"(r[0]), "=r"(r[1]), "=r"(r[2]), "=r"(r[3]) : "r"(addr));
}
__device__ __forceinline__ unsigned smem_u32(const void* p) {
    unsigned a;
    asm("{.reg .u64 t; cvta.to.shared.u64 t, %1; cvt.u32.u64 %0, t;}" : "=r"(a) : "l"(p));
    return a;
}
__device__ __forceinline__ void cpa16(unsigned dst, const void* src) {
    asm volatile("cp.async.cg.shared.global [%0], [%1], 16;" :: "r"(dst), "l"(src) : "memory");
}
__device__ __forceinline__ void cp_commit() { asm volatile("cp.async.commit_group;" ::: "memory"); }
__device__ __forceinline__ void cp_wait0()  { asm volatile("cp.async.wait_group 0;" ::: "memory"); }
__device__ __forceinline__ void cp_wait1()  { asm volatile("cp.async.wait_group 1;" ::: "memory"); }
__device__ __forceinline__ void cp_wait2()  { asm volatile("cp.async.wait_group 2;" ::: "memory"); }

// -------------------- fp32 -> fp16 convert -------------------------------------------
__global__ __launch_bounds__(256)
void f2h(const float* __restrict__ s, __half* __restrict__ d, int n)
{
    int i = (blockIdx.x * 256 + threadIdx.x) * 8;
    if (i < n) {
        float4 a = *(const float4*)(s + i);
        float4 b = *(const float4*)(s + i + 4);
        uint2 ua = f4h(a), ub = f4h(b);
        *(uint4*)(d + i) = make_uint4(ua.x, ua.y, ub.x, ub.y);
    }
}

// -------------------- rotary table (fp64 trig, computed once per call) ----------------
__global__ __launch_bounds__(256)
void rot_build()
{
    int idx = blockIdx.x * 256 + threadIdx.x;   // 0..65535
    int t = idx >> 5, j = idx & 31;
    float tj = (float)j / 31.0f;
    float fr = (float)exp2(-10.0 * (double)tj);
    float th = (float)t * fr;
    g_rot[t * 64 + 2 * j]     = (float)cos((double)th);
    g_rot[t * 64 + 2 * j + 1] = (float)sin((double)th);
}

// -------------------- GEMM (fp16 TC, cp.async 3-stage): C = A @ B^T ------------------
// BM=64, BN=128, BK=64, 256 threads = 8 warps (2m x 4n), warp tile 32x32.
// SMEM rows: 64 halfs + 8 pad = 36 u32 -> conflict-free ldmatrix.
#define GSM_A(s) ((s) * 2304)
#define GSM_B(s) (3 * 2304 + (s) * 4608)
#define GEMM_SMEM_BYTES ((3 * 2304 + 3 * 4608) * 4)

__global__ __launch_bounds__(256)
void gemm_h2(const __half* __restrict__ A, const __half* __restrict__ B,
             float* __restrict__ C, int M, int N, int K)
{
    extern __shared__ unsigned gsm[];
    const unsigned smb = smem_u32(gsm);
    const int tid  = threadIdx.x;
    const int lane = tid & 31;
    const int wid  = tid >> 5;
    const int wm   = wid >> 2;
    const int wn   = wid & 3;
    const int m0   = blockIdx.y * 64;
    const int n0   = blockIdx.x * 128;

    const int arow = (lane & 7) + ((lane >> 3) & 1) * 8;
    const int acol = (lane >> 4) * 4;
    const int brow = (lane & 7) + ((lane >> 4) & 1) * 8;
    const int bcol = ((lane >> 3) & 1) * 4;
    const int NK   = K >> 6;

    auto loadAB = [&](int it, int s) {
        const __half* Ab = A + (size_t)m0 * K + it * 64;
        const __half* Bb = B + (size_t)n0 * K + it * 64;
        unsigned da = smb + GSM_A(s) * 4;
        unsigned db = smb + GSM_B(s) * 4;
#pragma unroll
        for (int p = 0; p < 2; p++) {
            int id = tid + p * 256;
            int row = id >> 3, o = id & 7;
            cpa16(da + row * 144u + o * 16u, Ab + (size_t)row * K + o * 8);
        }
#pragma unroll
        for (int p = 0; p < 4; p++) {
            int id = tid + p * 256;
            int row = id >> 3, o = id & 7;
            cpa16(db + row * 144u + o * 16u, Bb + (size_t)row * K + o * 8);
        }
    };

    float acc[2][4][4];
#pragma unroll
    for (int i = 0; i < 2; i++)
#pragma unroll
        for (int j = 0; j < 4; j++)
#pragma unroll
            for (int r = 0; r < 4; r++) acc[i][j][r] = 0.0f;

    loadAB(0, 0); cp_commit();
    loadAB(1, 1); cp_commit();

    for (int it = 0; it < NK; it++) {
        const int s = it % 3;
        if (it + 1 < NK) cp_wait1(); else cp_wait0();
        __syncthreads();
        if (it + 2 < NK) { loadAB(it + 2, (it + 2) % 3); cp_commit(); }

        const unsigned ab = smb + GSM_A(s) * 4;
        const unsigned bb = smb + GSM_B(s) * 4;
#pragma unroll
        for (int ks = 0; ks < 4; ks++) {
            unsigned a[2][4], bq[2][4];
#pragma unroll
            for (int mi = 0; mi < 2; mi++)
                ldm4(a[mi], ab + ((wm * 32 + mi * 16 + arow) * 36 + ks * 8 + acol) * 4);
#pragma unroll
            for (int jp = 0; jp < 2; jp++)
                ldm4(bq[jp], bb + ((wn * 32 + jp * 16 + brow) * 36 + ks * 8 + bcol) * 4);
#pragma unroll
            for (int j = 0; j < 4; j++) {
                const unsigned* pb = &bq[j >> 1][(j & 1) * 2];
                mma_h(acc[0][j], a[0], pb);
                mma_h(acc[1][j], a[1], pb);
            }
        }
    }

    const int rq = lane >> 2, cq = lane & 3;
#pragma unroll
    for (int mi = 0; mi < 2; mi++) {
        int r = m0 + wm * 32 + mi * 16 + rq;
#pragma unroll
        for (int j = 0; j < 4; j++) {
            int cn = n0 + wn * 32 + j * 8 + 2 * cq;
            *(float2*)&C[(size_t)r * N + cn]       = make_float2(acc[mi][j][0], acc[mi][j][1]);
            *(float2*)&C[(size_t)(r + 8) * N + cn] = make_float2(acc[mi][j][2], acc[mi][j][3]);
        }
    }
}

// -------------------- q/k transform: rmsnorm + rotary (table) -> fp16 ----------------
__global__ __launch_bounds__(128)
void qk_transform()
{
    const int t = blockIdx.x;
    const int h = blockIdx.y;
    const int c = threadIdx.x;
    const int lane = c & 31;
    const int wid  = c >> 5;

    const float* base = g_qkv + (size_t)t * (3 * DIM_);
    float qv = base[       h * HD + c];
    float kv = base[DIM_ + h * HD + c];

    float sq = qv * qv;
    float sk = kv * kv;
#pragma unroll
    for (int off = 16; off >= 1; off >>= 1) {
        sq += __shfl_xor_sync(0xffffffffu, sq, off);
        sk += __shfl_xor_sync(0xffffffffu, sk, off);
    }
    __shared__ float wq[4], wk[4], rq, rk, qn[128], kn[128];
    if (lane == 0) { wq[wid] = sq; wk[wid] = sk; }
    __syncthreads();
    if (c == 0) {
        rq = rsqrtf((wq[0] + wq[1] + wq[2] + wq[3]) * (1.0f / 128.0f) + RMS_EPS);
        rk = rsqrtf((wk[0] + wk[1] + wk[2] + wk[3]) * (1.0f / 128.0f) + RMS_EPS);
    }
    __syncthreads();
    qn[c] = qv * rq;
    kn[c] = kv * rk;
    __syncthreads();

    int j = c & 63;
    float cosv = 1.0f, sinv = 0.0f;
    if (j < 32) {
        cosv = g_rot[t * 64 + 2 * j];
        sinv = g_rot[t * 64 + 2 * j + 1];
    }

    float qo, ko;
    if (c < 64) {
        qo =  qn[c] * cosv + qn[c + 64] * sinv;
        ko =  kn[c] * cosv + kn[c + 64] * sinv;
    } else {
        qo = -qn[c - 64] * sinv + qn[c] * cosv;
        ko = -kn[c - 64] * sinv + kn[c] * cosv;
    }

    size_t oidx = ((size_t)h * T_SEQ + t) * HD + c;
    g_qh[oidx] = __float2half_rn(qo);
    g_kh[oidx] = __float2half_rn(ko);
}

// -------------------- v mix + transpose: g_vt[h][d][t] -------------------------------
__global__ __launch_bounds__(128)
void vmix_trans(const float* __restrict__ ve, const float* __restrict__ lambdas)
{
    __shared__ __half tile[64 * 136];
    const int h  = blockIdx.y;
    const int t0 = blockIdx.x * 64;
    const int tid = threadIdx.x;
    const float l0 = lambdas[0], l1 = lambdas[1];

#pragma unroll
    for (int p = 0; p < 16; p++) {
        int f = tid + p * 128;
        int row = f >> 5, c4 = (f & 31) * 4;
        float4 v = *(const float4*)(g_qkv + (size_t)(t0 + row) * (3 * DIM_) + 2 * DIM_ + h * HD + c4);
        float4 e = *(const float4*)(ve + (size_t)(t0 + row) * DIM_ + h * HD + c4);
        tile[row * 136 + c4 + 0] = __float2half_rn(l0 * v.x + l1 * e.x);
        tile[row * 136 + c4 + 1] = __float2half_rn(l0 * v.y + l1 * e.y);
        tile[row * 136 + c4 + 2] = __float2half_rn(l0 * v.z + l1 * e.z);
        tile[row * 136 + c4 + 3] = __float2half_rn(l0 * v.w + l1 * e.w);
    }
    __syncthreads();

#pragma unroll
    for (int p = 0; p < 8; p++) {
        int f = tid + p * 128;
        int d = f >> 3, s8 = (f & 7) * 8;
        __half tmp[8];
#pragma unroll
        for (int i = 0; i < 8; i++) tmp[i] = tile[(s8 + i) * 136 + d];
        *(uint4*)(g_vt + ((size_t)h * HD + d) * T_SEQ + t0 + s8) = *(uint4*)tmp;
    }
}

// -------------------- flash attention: 2 q-tiles/block, 8 warps, 3-buf KV ------------
// 128 blocks, 256 threads. Block b: head = b&7, pr = b>>3.
// Warp group 0 (warps 0-3): q-tile pr (light). Group 1 (warps 4-7): q-tile 31-pr.
// SMEM u32: Q[2 x 4352] | K[3 x 4352] @8704 | V[3 x 4608] @21760; total 35584 words.
#define ATT_SMEM_BYTES (35584 * 4)

__global__ __launch_bounds__(256)
void attn_h()
{
    extern __shared__ unsigned sm[];
    const unsigned smb = smem_u32(sm);
    const int tid  = threadIdx.x;
    const int lane = tid & 31;
    const int wg   = tid >> 7;          // warp group
    const int w    = (tid >> 5) & 3;    // warp in group
    const int rq   = lane >> 2;
    const int cq   = lane & 3;
    const int h    = blockIdx.x & 7;
    const int pr   = blockIdx.x >> 3;
    const int myqt = wg ? (31 - pr) : pr;
    const int qmax = 31 - pr;
    const int q0   = myqt * 64;

    const __half* qh = g_qh + (size_t)h * T_SEQ * HD;
    const __half* kh = g_kh + (size_t)h * T_SEQ * HD;
    const __half* vt = g_vt + (size_t)h * HD * T_SEQ;

    const int arow = (lane & 7) + ((lane >> 3) & 1) * 8;
    const int acol = (lane >> 4) * 4;
    const int brow = (lane & 7) + ((lane >> 4) & 1) * 8;
    const int bcol = ((lane >> 3) & 1) * 4;

    auto loadKV = [&](int t, int s) {
        const int s0 = t * 64;
        const unsigned kb = smb + (8704u + s * 4352u) * 4u;
        const unsigned vb = smb + (21760u + s * 4608u) * 4u;
#pragma unroll
        for (int p = 0; p < 4; p++) {
            int id = tid + p * 256;
            int row = id >> 4, o = id & 15;
            cpa16(kb + row * 272u + o * 16u, kh + (size_t)(s0 + row) * HD + o * 8);
        }
#pragma unroll
        for (int p = 0; p < 4; p++) {
            int id = tid + p * 256;
            int d = id >> 3, o = id & 7;
            cpa16(vb + d * 144u + o * 16u, vt + (size_t)d * T_SEQ + s0 + o * 8);
        }
    };

    // Q load: each group loads its own tile
    {
        int ltid = tid & 127;
#pragma unroll
        for (int p = 0; p < 8; p++) {
            int id = ltid + p * 128;
            int row = id >> 4, o = id & 15;
            cpa16(smb + (wg * 4352u + row * 68u) * 4u + o * 16u,
                  qh + (size_t)(q0 + row) * HD + o * 8);
        }
    }
    cp_commit();
    loadKV(0, 0); cp_commit();
    loadKV(1, 1); cp_commit();

    cp_wait2();          // Q done (KV0, KV1 may be pending)
    __syncthreads();

    unsigned qa[8][4];
#pragma unroll
    for (int ks = 0; ks < 8; ks++)
        ldm4(qa[ks], smb + (wg * 4352u + (w * 16 + arow) * 68u + ks * 8 + acol) * 4);

    float m0 = -INFINITY, m1 = -INFINITY, l0 = 0.0f, l1 = 0.0f;
    float O[16][4];
#pragma unroll
    for (int nf = 0; nf < 16; nf++)
#pragma unroll
        for (int r = 0; r < 4; r++) O[nf][r] = 0.0f;

    for (int t = 0; t <= qmax; t++) {
        if (t < qmax) cp_wait1(); else cp_wait0();   // KV(t) complete
        __syncthreads();                             // visible; prev compute done
        if (t + 2 <= qmax) { loadKV(t + 2, (t + 2) % 3); cp_commit(); }

        if (t <= myqt) {
            const int s = t % 3;
            const unsigned kb = smb + (8704u + s * 4352u) * 4u;
            const unsigned vb = smb + (21760u + s * 4608u) * 4u;

            // ---- S = Q K^T ----
            float sc[8][4];
#pragma unroll
            for (int nf = 0; nf < 8; nf++)
#pragma unroll
                for (int r = 0; r < 4; r++) sc[nf][r] = 0.0f;

#pragma unroll
            for (int ks = 0; ks < 8; ks++) {
#pragma unroll
                for (int np = 0; np < 4; np++) {
                    unsigned kq[4];
                    ldm4(kq, kb + ((np * 16 + brow) * 68u + ks * 8 + bcol) * 4);
                    mma_h(sc[2 * np],     qa[ks], &kq[0]);
                    mma_h(sc[2 * np + 1], qa[ks], &kq[2]);
                }
            }

            // scale into log2 domain + causal mask on diagonal tile
            const int r0l = w * 16 + rq, r1l = r0l + 8;
#pragma unroll
            for (int nf = 0; nf < 8; nf++) {
                sc[nf][0] *= C_SC; sc[nf][1] *= C_SC;
                sc[nf][2] *= C_SC; sc[nf][3] *= C_SC;
            }
            if (t == myqt) {
#pragma unroll
                for (int nf = 0; nf < 8; nf++) {
                    int c0 = nf * 8 + 2 * cq;
                    if (c0     > r0l) sc[nf][0] = -INFINITY;
                    if (c0 + 1 > r0l) sc[nf][1] = -INFINITY;
                    if (c0     > r1l) sc[nf][2] = -INFINITY;
                    if (c0 + 1 > r1l) sc[nf][3] = -INFINITY;
                }
            }

            // ---- warp-local row max ----
            float mx0 = -INFINITY, mx1 = -INFINITY;
#pragma unroll
            for (int nf = 0; nf < 8; nf++) {
                mx0 = fmaxf(mx0, fmaxf(sc[nf][0], sc[nf][1]));
                mx1 = fmaxf(mx1, fmaxf(sc[nf][2], sc[nf][3]));
            }
#pragma unroll
            for (int off = 1; off <= 2; off <<= 1) {
                mx0 = fmaxf(mx0, __shfl_xor_sync(0xffffffffu, mx0, off));
                mx1 = fmaxf(mx1, __shfl_xor_sync(0xffffffffu, mx1, off));
            }
            const float nm0 = fmaxf(m0, mx0);
            const float nm1 = fmaxf(m1, mx1);

            // ---- exp (base-2), P stays in registers as fp16 fragments ----
            float rs0 = 0.0f, rs1 = 0.0f;
            unsigned ph[8][2];
#pragma unroll
            for (int nf = 0; nf < 8; nf++) {
                float p0 = exp2f(sc[nf][0] - nm0);
                float p1 = exp2f(sc[nf][1] - nm0);
                float p2 = exp2f(sc[nf][2] - nm1);
                float p3 = exp2f(sc[nf][3] - nm1);
                rs0 += p0 + p1;
                rs1 += p2 + p3;
                ph[nf][0] = packh2(p0, p1);
                ph[nf][1] = packh2(p2, p3);
            }
#pragma unroll
            for (int off = 1; off <= 2; off <<= 1) {
                rs0 += __shfl_xor_sync(0xffffffffu, rs0, off);
                rs1 += __shfl_xor_sync(0xffffffffu, rs1, off);
            }

            const float al0 = exp2f(m0 - nm0);
            const float al1 = exp2f(m1 - nm1);
            l0 = l0 * al0 + rs0;  m0 = nm0;
            l1 = l1 * al1 + rs1;  m1 = nm1;
#pragma unroll
            for (int nf = 0; nf < 16; nf++) {
                O[nf][0] *= al0; O[nf][1] *= al0;
                O[nf][2] *= al1; O[nf][3] *= al1;
            }

            // ---- O += P @ V ----
#pragma unroll
            for (int ks = 0; ks < 4; ks++) {
                unsigned a[4] = { ph[2 * ks][0], ph[2 * ks][1],
                                  ph[2 * ks + 1][0], ph[2 * ks + 1][1] };
#pragma unroll
                for (int np = 0; np < 8; np++) {
                    unsigned vq[4];
                    ldm4(vq, vb + ((np * 16 + brow) * 36u + ks * 8 + bcol) * 4);
                    mma_h(O[2 * np],     a, &vq[0]);
                    mma_h(O[2 * np + 1], a, &vq[2]);
                }
            }
        }
    }

    // epilogue -> fp16 y
    const float inv0 = 1.0f / l0;
    const float inv1 = 1.0f / l1;
    const int row0 = q0 + w * 16 + rq, row1 = row0 + 8;
#pragma unroll
    for (int nf = 0; nf < 16; nf++) {
        int col = h * HD + nf * 8 + 2 * cq;
        *(unsigned*)&g_yh[(size_t)row0 * DIM_ + col] = packh2(O[nf][0] * inv0, O[nf][1] * inv0);
        *(unsigned*)&g_yh[(size_t)row1 * DIM_ + col] = packh2(O[nf][2] * inv1, O[nf][3] * inv1);
    }
}

// -------------------- launch ---------------------------------------------------------
extern "C" void kernel_launch(void* const* d_in, const int* in_sizes, int n_in,
                              void* d_out, int out_size)
{
    const float* x        = (const float*)d_in[0];
    const float* ve       = (const float*)d_in[1];
    const float* qkv_w    = (const float*)d_in[2];
    const float* lambdas  = (const float*)d_in[3];
    const float* c_proj_w = (const float*)d_in[4];
    float* out = (float*)d_out;

    float  *p_qkv;
    __half *p_xh, *p_wqkv, *p_wproj, *p_yh;
    cudaGetSymbolAddress((void**)&p_qkv,   g_qkv);
    cudaGetSymbolAddress((void**)&p_xh,    g_xh);
    cudaGetSymbolAddress((void**)&p_wqkv,  g_wqkv);
    cudaGetSymbolAddress((void**)&p_wproj, g_wproj);
    cudaGetSymbolAddress((void**)&p_yh,    g_yh);

    // 0) converts + rotary table
    f2h<<<(T_SEQ * DIM_) / 2048, 256>>>(x, p_xh, T_SEQ * DIM_);
    f2h<<<(3 * DIM_ * DIM_) / 2048, 256>>>(qkv_w, p_wqkv, 3 * DIM_ * DIM_);
    f2h<<<(DIM_ * DIM_) / 2048, 256>>>(c_proj_w, p_wproj, DIM_ * DIM_);
    rot_build<<<256, 256>>>();

    // 1) QKV projection: g_qkv[2048,3072] = xh @ wqkv^T
    cudaFuncSetAttribute(gemm_h2, cudaFuncAttributeMaxDynamicSharedMemorySize, GEMM_SMEM_BYTES);
    gemm_h2<<<dim3(3 * DIM_ / 128, T_SEQ / 64), 256, GEMM_SMEM_BYTES>>>(
        p_xh, p_wqkv, p_qkv, T_SEQ, 3 * DIM_, DIM_);

    // 2) rmsnorm + rotary (q,k -> fp16); v mix + transpose (fp16)
    qk_transform<<<dim3(T_SEQ, NH), 128>>>();
    vmix_trans<<<dim3(T_SEQ / 64, NH), 128>>>(ve, lambdas);

    // 3) causal flash attention -> fp16 y
    cudaFuncSetAttribute(attn_h, cudaFuncAttributeMaxDynamicSharedMemorySize, ATT_SMEM_BYTES);
    attn_h<<<dim3(128), 256, ATT_SMEM_BYTES>>>();

    // 4) output projection: out = yh @ wproj^T
    gemm_h2<<<dim3(DIM_ / 128, T_SEQ / 64), 256, GEMM_SMEM_BYTES>>>(
        p_yh, p_wproj, out, T_SEQ, DIM_, DIM_);
}

// round 9
// speedup vs baseline: 3.1688x; 1.0821x over previous
#include <cuda_runtime.h>
#include <cuda_fp16.h>
#include <math.h>

#define T_SEQ 2048
#define DIM_   1024
#define NH     8
#define HD     128
#define RMS_EPS 1.1920929e-7f
#define C_SC (0.12f * 1.4426950408889634f)   // ATTN_SCALE * log2(e)

// -------------------- scratch (static device globals; no allocs) --------------------
__device__ float  g_qkv  [(size_t)T_SEQ * 3 * DIM_];  // [t][3072] fp32
__device__ __half g_xh   [(size_t)T_SEQ * DIM_];      // fp16 x
__device__ __half g_wqkv [(size_t)3 * DIM_ * DIM_];   // fp16 qkv_w
__device__ __half g_wproj[(size_t)DIM_ * DIM_];       // fp16 c_proj_w
__device__ __half g_qh   [(size_t)NH * T_SEQ * HD];   // [h][t][d]
__device__ __half g_kh   [(size_t)NH * T_SEQ * HD];   // [h][t][d]
__device__ __half g_vt   [(size_t)NH * HD * T_SEQ];   // [h][d][t]
__device__ __half g_yh   [(size_t)T_SEQ * DIM_];      // attention out, fp16
__device__ float  g_rot  [(size_t)T_SEQ * 64];        // [t][2*j]=cos, [t][2*j+1]=sin, j<32

// -------------------- helpers --------------------------------------------------------
__device__ __forceinline__ uint2 f4h(float4 v) {
    uint2 r;
    asm("cvt.rn.f16x2.f32 %0, %1, %2;" : "=r"(r.x) : "f"(v.y), "f"(v.x));
    asm("cvt.rn.f16x2.f32 %0, %1, %2;" : "=r"(r.y) : "f"(v.w), "f"(v.z));
    return r;
}
__device__ __forceinline__ unsigned packh2(float lo, float hi) {
    unsigned r;
    asm("cvt.rn.f16x2.f32 %0, %1, %2;" : "=r"(r) : "f"(hi), "f"(lo));
    return r;
}
__device__ __forceinline__ void mma_h(float c[4], const unsigned a[4], const unsigned* b) {
    asm volatile(
        "mma.sync.aligned.m16n8k16.row.col.f32.f16.f16.f32 "
        "{%0,%1,%2,%3}, {%4,%5,%6,%7}, {%8,%9}, {%0,%1,%2,%3};"
        : "+f"(c[0]), "+f"(c[1]), "+f"(c[2]), "+f"(c[3])
        : "r"(a[0]), "r"(a[1]), "r"(a[2]), "r"(a[3]), "r"(b[0]), "r"(b[1]));
}
__device__ __forceinline__ void ldm4(unsigned r[4], unsigned addr) {
    asm volatile("ldmatrix.sync.aligned.m8n8.x4.shared.b16 {%0,%1,%2,%3}, [%4];"
                 : "=r"(r[0]), "=r"(r[1]), "=r"(r[2]), "=r"(r[3]) : "r"(addr));
}
__device__ __forceinline__ unsigned smem_u32(const void* p) {
    unsigned a;
    asm("{.reg .u64 t; cvta.to.shared.u64 t, %1; cvt.u32.u64 %0, t;}" : "=r"(a) : "l"(p));
    return a;
}
__device__ __forceinline__ void cpa16(unsigned dst, const void* src) {
    asm volatile("cp.async.cg.shared.global [%0], [%1], 16;" :: "r"(dst), "l"(src) : "memory");
}
__device__ __forceinline__ void cp_commit() { asm volatile("cp.async.commit_group;" ::: "memory"); }
__device__ __forceinline__ void cp_wait0()  { asm volatile("cp.async.wait_group 0;" ::: "memory"); }
__device__ __forceinline__ void cp_wait1()  { asm volatile("cp.async.wait_group 1;" ::: "memory"); }
__device__ __forceinline__ void cp_wait2()  { asm volatile("cp.async.wait_group 2;" ::: "memory"); }

// -------------------- fp32 -> fp16 convert -------------------------------------------
__global__ __launch_bounds__(256)
void f2h(const float* __restrict__ s, __half* __restrict__ d, int n)
{
    int i = (blockIdx.x * 256 + threadIdx.x) * 8;
    if (i < n) {
        float4 a = *(const float4*)(s + i);
        float4 b = *(const float4*)(s + i + 4);
        uint2 ua = f4h(a), ub = f4h(b);
        *(uint4*)(d + i) = make_uint4(ua.x, ua.y, ub.x, ub.y);
    }
}

// -------------------- rotary table: fp32 Cody-Waite sincos ----------------------------
// fr kept bit-identical to previous rounds (double exp2, fp32-rounded).
// theta = t*fr in fp32 (matches reference); sincos via fp32 range reduction:
//   k = rint(theta * 2/pi) (k <= 1304), r = theta - k*C1 - k*C2 with C1 exact product.
__global__ __launch_bounds__(256)
void rot_build()
{
    int idx = blockIdx.x * 256 + threadIdx.x;   // 0..65535
    int t = idx >> 5, j = idx & 31;
    float tj = (float)j / 31.0f;
    float fr = (float)exp2(-10.0 * (double)tj);   // bit-identical fr
    float th = (float)t * fr;

    const float C1 = 1.5703125f;                  // 8-bit mantissa: k*C1 exact
    const float C2 = 4.83826794897e-4f;           // pi/2 - C1
    float kf = rintf(th * 0.63661977236758134f);  // 2/pi
    int   ki = (int)kf;
    float r  = fmaf(-kf, C1, th);                 // exact
    r = fmaf(-kf, C2, r);                         // residual error ~4e-8 rad

    float r2 = r * r;
    // |r| <= pi/4 minimax polys (fp32, ~1e-7 abs err)
    float sp = fmaf(r2, fmaf(r2, fmaf(r2, 2.75573137e-6f, -1.98412698e-4f),
                             8.33333376e-3f), -1.66666672e-1f);
    sp = fmaf(r * r2, sp, r);
    float cp = fmaf(r2, fmaf(r2, fmaf(r2, fmaf(r2, 2.44331571e-5f, -1.38873162e-3f),
                             4.16666418e-2f), -0.5f), 1.0f);

    float cosv, sinv;
    switch (ki & 3) {
        case 0:  cosv =  cp; sinv =  sp; break;
        case 1:  cosv = -sp; sinv =  cp; break;
        case 2:  cosv = -cp; sinv = -sp; break;
        default: cosv =  sp; sinv = -cp; break;
    }
    g_rot[t * 64 + 2 * j]     = cosv;
    g_rot[t * 64 + 2 * j + 1] = sinv;
}

// -------------------- GEMM (fp16 TC, cp.async 3-stage): C = A @ B^T ------------------
#define GSM_A(s) ((s) * 2304)
#define GSM_B(s) (3 * 2304 + (s) * 4608)
#define GEMM_SMEM_BYTES ((3 * 2304 + 3 * 4608) * 4)

__global__ __launch_bounds__(256)
void gemm_h2(const __half* __restrict__ A, const __half* __restrict__ B,
             float* __restrict__ C, int M, int N, int K)
{
    extern __shared__ unsigned gsm[];
    const unsigned smb = smem_u32(gsm);
    const int tid  = threadIdx.x;
    const int lane = tid & 31;
    const int wid  = tid >> 5;
    const int wm   = wid >> 2;
    const int wn   = wid & 3;
    const int m0   = blockIdx.y * 64;
    const int n0   = blockIdx.x * 128;

    const int arow = (lane & 7) + ((lane >> 3) & 1) * 8;
    const int acol = (lane >> 4) * 4;
    const int brow = (lane & 7) + ((lane >> 4) & 1) * 8;
    const int bcol = ((lane >> 3) & 1) * 4;
    const int NK   = K >> 6;

    auto loadAB = [&](int it, int s) {
        const __half* Ab = A + (size_t)m0 * K + it * 64;
        const __half* Bb = B + (size_t)n0 * K + it * 64;
        unsigned da = smb + GSM_A(s) * 4;
        unsigned db = smb + GSM_B(s) * 4;
#pragma unroll
        for (int p = 0; p < 2; p++) {
            int id = tid + p * 256;
            int row = id >> 3, o = id & 7;
            cpa16(da + row * 144u + o * 16u, Ab + (size_t)row * K + o * 8);
        }
#pragma unroll
        for (int p = 0; p < 4; p++) {
            int id = tid + p * 256;
            int row = id >> 3, o = id & 7;
            cpa16(db + row * 144u + o * 16u, Bb + (size_t)row * K + o * 8);
        }
    };

    float acc[2][4][4];
#pragma unroll
    for (int i = 0; i < 2; i++)
#pragma unroll
        for (int j = 0; j < 4; j++)
#pragma unroll
            for (int r = 0; r < 4; r++) acc[i][j][r] = 0.0f;

    loadAB(0, 0); cp_commit();
    loadAB(1, 1); cp_commit();

    for (int it = 0; it < NK; it++) {
        const int s = it % 3;
        if (it + 1 < NK) cp_wait1(); else cp_wait0();
        __syncthreads();
        if (it + 2 < NK) { loadAB(it + 2, (it + 2) % 3); cp_commit(); }

        const unsigned ab = smb + GSM_A(s) * 4;
        const unsigned bb = smb + GSM_B(s) * 4;
#pragma unroll
        for (int ks = 0; ks < 4; ks++) {
            unsigned a[2][4], bq[2][4];
#pragma unroll
            for (int mi = 0; mi < 2; mi++)
                ldm4(a[mi], ab + ((wm * 32 + mi * 16 + arow) * 36 + ks * 8 + acol) * 4);
#pragma unroll
            for (int jp = 0; jp < 2; jp++)
                ldm4(bq[jp], bb + ((wn * 32 + jp * 16 + brow) * 36 + ks * 8 + bcol) * 4);
#pragma unroll
            for (int j = 0; j < 4; j++) {
                const unsigned* pb = &bq[j >> 1][(j & 1) * 2];
                mma_h(acc[0][j], a[0], pb);
                mma_h(acc[1][j], a[1], pb);
            }
        }
    }

    const int rq = lane >> 2, cq = lane & 3;
#pragma unroll
    for (int mi = 0; mi < 2; mi++) {
        int r = m0 + wm * 32 + mi * 16 + rq;
#pragma unroll
        for (int j = 0; j < 4; j++) {
            int cn = n0 + wn * 32 + j * 8 + 2 * cq;
            *(float2*)&C[(size_t)r * N + cn]       = make_float2(acc[mi][j][0], acc[mi][j][1]);
            *(float2*)&C[(size_t)(r + 8) * N + cn] = make_float2(acc[mi][j][2], acc[mi][j][3]);
        }
    }
}

// -------------------- q/k transform: one warp per (t,h), no SMEM ---------------------
// 2048 blocks x 256 threads = 16384 warps = T_SEQ * NH.
__global__ __launch_bounds__(256)
void qk_transform()
{
    const int lane = threadIdx.x & 31;
    const int gid  = blockIdx.x * 8 + (threadIdx.x >> 5);
    const int t = gid >> 3;
    const int h = gid & 7;

    const float* base = g_qkv + (size_t)t * (3 * DIM_) + h * HD + lane * 4;
    float4 q4 = *(const float4*)(base);
    float4 k4 = *(const float4*)(base + DIM_);

    float sq = q4.x * q4.x + q4.y * q4.y + q4.z * q4.z + q4.w * q4.w;
    float sk = k4.x * k4.x + k4.y * k4.y + k4.z * k4.z + k4.w * k4.w;
#pragma unroll
    for (int off = 16; off >= 1; off >>= 1) {
        sq += __shfl_xor_sync(0xffffffffu, sq, off);
        sk += __shfl_xor_sync(0xffffffffu, sk, off);
    }
    const float rq = rsqrtf(sq * (1.0f / 128.0f) + RMS_EPS);
    const float rk = rsqrtf(sk * (1.0f / 128.0f) + RMS_EPS);

    float qn[4] = { q4.x * rq, q4.y * rq, q4.z * rq, q4.w * rq };
    float kn[4] = { k4.x * rk, k4.y * rk, k4.z * rk, k4.w * rk };

    // rotary pair: partner channel c^64 lives in lane^16
    float qp[4], kp[4];
#pragma unroll
    for (int i = 0; i < 4; i++) {
        qp[i] = __shfl_xor_sync(0xffffffffu, qn[i], 16);
        kp[i] = __shfl_xor_sync(0xffffffffu, kn[i], 16);
    }

    const int L = lane & 15;             // j block: j = L*4 + i (valid for L<8)
    float cs[4], sn[4];
    if (L < 8) {
        const float* rt = g_rot + t * 64 + L * 8;
        float4 a = *(const float4*)(rt);
        float4 b = *(const float4*)(rt + 4);
        cs[0] = a.x; sn[0] = a.y; cs[1] = a.z; sn[1] = a.w;
        cs[2] = b.x; sn[2] = b.y; cs[3] = b.z; sn[3] = b.w;
    } else {
#pragma unroll
        for (int i = 0; i < 4; i++) { cs[i] = 1.0f; sn[i] = 0.0f; }
    }
    const float sgn = (lane < 16) ? 1.0f : -1.0f;

    float qo[4], ko[4];
#pragma unroll
    for (int i = 0; i < 4; i++) {
        qo[i] = fmaf(sgn * qp[i], sn[i], qn[i] * cs[i]);
        ko[i] = fmaf(sgn * kp[i], sn[i], kn[i] * cs[i]);
    }

    size_t oidx = ((size_t)h * T_SEQ + t) * HD + lane * 4;
    *(uint2*)&g_qh[oidx] = make_uint2(packh2(qo[0], qo[1]), packh2(qo[2], qo[3]));
    *(uint2*)&g_kh[oidx] = make_uint2(packh2(ko[0], ko[1]), packh2(ko[2], ko[3]));
}

// -------------------- v mix + transpose: g_vt[h][d][t] -------------------------------
__global__ __launch_bounds__(128)
void vmix_trans(const float* __restrict__ ve, const float* __restrict__ lambdas)
{
    __shared__ __half tile[64 * 136];
    const int h  = blockIdx.y;
    const int t0 = blockIdx.x * 64;
    const int tid = threadIdx.x;
    const float l0 = lambdas[0], l1 = lambdas[1];

#pragma unroll
    for (int p = 0; p < 16; p++) {
        int f = tid + p * 128;
        int row = f >> 5, c4 = (f & 31) * 4;
        float4 v = *(const float4*)(g_qkv + (size_t)(t0 + row) * (3 * DIM_) + 2 * DIM_ + h * HD + c4);
        float4 e = *(const float4*)(ve + (size_t)(t0 + row) * DIM_ + h * HD + c4);
        tile[row * 136 + c4 + 0] = __float2half_rn(l0 * v.x + l1 * e.x);
        tile[row * 136 + c4 + 1] = __float2half_rn(l0 * v.y + l1 * e.y);
        tile[row * 136 + c4 + 2] = __float2half_rn(l0 * v.z + l1 * e.z);
        tile[row * 136 + c4 + 3] = __float2half_rn(l0 * v.w + l1 * e.w);
    }
    __syncthreads();

#pragma unroll
    for (int p = 0; p < 8; p++) {
        int f = tid + p * 128;
        int d = f >> 3, s8 = (f & 7) * 8;
        __half tmp[8];
#pragma unroll
        for (int i = 0; i < 8; i++) tmp[i] = tile[(s8 + i) * 136 + d];
        *(uint4*)(g_vt + ((size_t)h * HD + d) * T_SEQ + t0 + s8) = *(uint4*)tmp;
    }
}

// -------------------- flash attention: 2 q-tiles/block, 8 warps, 3-buf KV ------------
#define ATT_SMEM_BYTES (35584 * 4)

__global__ __launch_bounds__(256)
void attn_h()
{
    extern __shared__ unsigned sm[];
    const unsigned smb = smem_u32(sm);
    const int tid  = threadIdx.x;
    const int lane = tid & 31;
    const int wg   = tid >> 7;
    const int w    = (tid >> 5) & 3;
    const int rq   = lane >> 2;
    const int cq   = lane & 3;
    const int h    = blockIdx.x & 7;
    const int pr   = blockIdx.x >> 3;
    const int myqt = wg ? (31 - pr) : pr;
    const int qmax = 31 - pr;
    const int q0   = myqt * 64;

    const __half* qh = g_qh + (size_t)h * T_SEQ * HD;
    const __half* kh = g_kh + (size_t)h * T_SEQ * HD;
    const __half* vt = g_vt + (size_t)h * HD * T_SEQ;

    const int arow = (lane & 7) + ((lane >> 3) & 1) * 8;
    const int acol = (lane >> 4) * 4;
    const int brow = (lane & 7) + ((lane >> 4) & 1) * 8;
    const int bcol = ((lane >> 3) & 1) * 4;

    auto loadKV = [&](int t, int s) {
        const int s0 = t * 64;
        const unsigned kb = smb + (8704u + s * 4352u) * 4u;
        const unsigned vb = smb + (21760u + s * 4608u) * 4u;
#pragma unroll
        for (int p = 0; p < 4; p++) {
            int id = tid + p * 256;
            int row = id >> 4, o = id & 15;
            cpa16(kb + row * 272u + o * 16u, kh + (size_t)(s0 + row) * HD + o * 8);
        }
#pragma unroll
        for (int p = 0; p < 4; p++) {
            int id = tid + p * 256;
            int d = id >> 3, o = id & 7;
            cpa16(vb + d * 144u + o * 16u, vt + (size_t)d * T_SEQ + s0 + o * 8);
        }
    };

    {
        int ltid = tid & 127;
#pragma unroll
        for (int p = 0; p < 8; p++) {
            int id = ltid + p * 128;
            int row = id >> 4, o = id & 15;
            cpa16(smb + (wg * 4352u + row * 68u) * 4u + o * 16u,
                  qh + (size_t)(q0 + row) * HD + o * 8);
        }
    }
    cp_commit();
    loadKV(0, 0); cp_commit();
    loadKV(1, 1); cp_commit();

    cp_wait2();
    __syncthreads();

    unsigned qa[8][4];
#pragma unroll
    for (int ks = 0; ks < 8; ks++)
        ldm4(qa[ks], smb + (wg * 4352u + (w * 16 + arow) * 68u + ks * 8 + acol) * 4);

    float m0 = -INFINITY, m1 = -INFINITY, l0 = 0.0f, l1 = 0.0f;
    float O[16][4];
#pragma unroll
    for (int nf = 0; nf < 16; nf++)
#pragma unroll
        for (int r = 0; r < 4; r++) O[nf][r] = 0.0f;

    for (int t = 0; t <= qmax; t++) {
        if (t < qmax) cp_wait1(); else cp_wait0();
        __syncthreads();
        if (t + 2 <= qmax) { loadKV(t + 2, (t + 2) % 3); cp_commit(); }

        if (t <= myqt) {
            const int s = t % 3;
            const unsigned kb = smb + (8704u + s * 4352u) * 4u;
            const unsigned vb = smb + (21760u + s * 4608u) * 4u;

            float sc[8][4];
#pragma unroll
            for (int nf = 0; nf < 8; nf++)
#pragma unroll
                for (int r = 0; r < 4; r++) sc[nf][r] = 0.0f;

#pragma unroll
            for (int ks = 0; ks < 8; ks++) {
#pragma unroll
                for (int np = 0; np < 4; np++) {
                    unsigned kq[4];
                    ldm4(kq, kb + ((np * 16 + brow) * 68u + ks * 8 + bcol) * 4);
                    mma_h(sc[2 * np],     qa[ks], &kq[0]);
                    mma_h(sc[2 * np + 1], qa[ks], &kq[2]);
                }
            }

            const int r0l = w * 16 + rq, r1l = r0l + 8;
#pragma unroll
            for (int nf = 0; nf < 8; nf++) {
                sc[nf][0] *= C_SC; sc[nf][1] *= C_SC;
                sc[nf][2] *= C_SC; sc[nf][3] *= C_SC;
            }
            if (t == myqt) {
#pragma unroll
                for (int nf = 0; nf < 8; nf++) {
                    int c0 = nf * 8 + 2 * cq;
                    if (c0     > r0l) sc[nf][0] = -INFINITY;
                    if (c0 + 1 > r0l) sc[nf][1] = -INFINITY;
                    if (c0     > r1l) sc[nf][2] = -INFINITY;
                    if (c0 + 1 > r1l) sc[nf][3] = -INFINITY;
                }
            }

            float mx0 = -INFINITY, mx1 = -INFINITY;
#pragma unroll
            for (int nf = 0; nf < 8; nf++) {
                mx0 = fmaxf(mx0, fmaxf(sc[nf][0], sc[nf][1]));
                mx1 = fmaxf(mx1, fmaxf(sc[nf][2], sc[nf][3]));
            }
#pragma unroll
            for (int off = 1; off <= 2; off <<= 1) {
                mx0 = fmaxf(mx0, __shfl_xor_sync(0xffffffffu, mx0, off));
                mx1 = fmaxf(mx1, __shfl_xor_sync(0xffffffffu, mx1, off));
            }
            const float nm0 = fmaxf(m0, mx0);
            const float nm1 = fmaxf(m1, mx1);

            float rs0 = 0.0f, rs1 = 0.0f;
            unsigned ph[8][2];
#pragma unroll
            for (int nf = 0; nf < 8; nf++) {
                float p0 = exp2f(sc[nf][0] - nm0);
                float p1 = exp2f(sc[nf][1] - nm0);
                float p2 = exp2f(sc[nf][2] - nm1);
                float p3 = exp2f(sc[nf][3] - nm1);
                rs0 += p0 + p1;
                rs1 += p2 + p3;
                ph[nf][0] = packh2(p0, p1);
                ph[nf][1] = packh2(p2, p3);
            }
#pragma unroll
            for (int off = 1; off <= 2; off <<= 1) {
                rs0 += __shfl_xor_sync(0xffffffffu, rs0, off);
                rs1 += __shfl_xor_sync(0xffffffffu, rs1, off);
            }

            const float al0 = exp2f(m0 - nm0);
            const float al1 = exp2f(m1 - nm1);
            l0 = l0 * al0 + rs0;  m0 = nm0;
            l1 = l1 * al1 + rs1;  m1 = nm1;
#pragma unroll
            for (int nf = 0; nf < 16; nf++) {
                O[nf][0] *= al0; O[nf][1] *= al0;
                O[nf][2] *= al1; O[nf][3] *= al1;
            }

#pragma unroll
            for (int ks = 0; ks < 4; ks++) {
                unsigned a[4] = { ph[2 * ks][0], ph[2 * ks][1],
                                  ph[2 * ks + 1][0], ph[2 * ks + 1][1] };
#pragma unroll
                for (int np = 0; np < 8; np++) {
                    unsigned vq[4];
                    ldm4(vq, vb + ((np * 16 + brow) * 36u + ks * 8 + bcol) * 4);
                    mma_h(O[2 * np],     a, &vq[0]);
                    mma_h(O[2 * np + 1], a, &vq[2]);
                }
            }
        }
    }

    const float inv0 = 1.0f / l0;
    const float inv1 = 1.0f / l1;
    const int row0 = q0 + w * 16 + rq, row1 = row0 + 8;
#pragma unroll
    for (int nf = 0; nf < 16; nf++) {
        int col = h * HD + nf * 8 + 2 * cq;
        *(unsigned*)&g_yh[(size_t)row0 * DIM_ + col] = packh2(O[nf][0] * inv0, O[nf][1] * inv0);
        *(unsigned*)&g_yh[(size_t)row1 * DIM_ + col] = packh2(O[nf][2] * inv1, O[nf][3] * inv1);
    }
}

// -------------------- launch ---------------------------------------------------------
extern "C" void kernel_launch(void* const* d_in, const int* in_sizes, int n_in,
                              void* d_out, int out_size)
{
    const float* x        = (const float*)d_in[0];
    const float* ve       = (const float*)d_in[1];
    const float* qkv_w    = (const float*)d_in[2];
    const float* lambdas  = (const float*)d_in[3];
    const float* c_proj_w = (const float*)d_in[4];
    float* out = (float*)d_out;

    float  *p_qkv;
    __half *p_xh, *p_wqkv, *p_wproj, *p_yh;
    cudaGetSymbolAddress((void**)&p_qkv,   g_qkv);
    cudaGetSymbolAddress((void**)&p_xh,    g_xh);
    cudaGetSymbolAddress((void**)&p_wqkv,  g_wqkv);
    cudaGetSymbolAddress((void**)&p_wproj, g_wproj);
    cudaGetSymbolAddress((void**)&p_yh,    g_yh);

    // 0) converts + rotary table
    f2h<<<(T_SEQ * DIM_) / 2048, 256>>>(x, p_xh, T_SEQ * DIM_);
    f2h<<<(3 * DIM_ * DIM_) / 2048, 256>>>(qkv_w, p_wqkv, 3 * DIM_ * DIM_);
    f2h<<<(DIM_ * DIM_) / 2048, 256>>>(c_proj_w, p_wproj, DIM_ * DIM_);
    rot_build<<<256, 256>>>();

    // 1) QKV projection
    cudaFuncSetAttribute(gemm_h2, cudaFuncAttributeMaxDynamicSharedMemorySize, GEMM_SMEM_BYTES);
    gemm_h2<<<dim3(3 * DIM_ / 128, T_SEQ / 64), 256, GEMM_SMEM_BYTES>>>(
        p_xh, p_wqkv, p_qkv, T_SEQ, 3 * DIM_, DIM_);

    // 2) rmsnorm + rotary (warp per (t,h)); v mix + transpose
    qk_transform<<<2048, 256>>>();
    vmix_trans<<<dim3(T_SEQ / 64, NH), 128>>>(ve, lambdas);

    // 3) causal flash attention -> fp16
    cudaFuncSetAttribute(attn_h, cudaFuncAttributeMaxDynamicSharedMemorySize, ATT_SMEM_BYTES);
    attn_h<<<dim3(128), 256, ATT_SMEM_BYTES>>>();

    // 4) output projection
    gemm_h2<<<dim3(DIM_ / 128, T_SEQ / 64), 256, GEMM_SMEM_BYTES>>>(
        p_yh, p_wproj, out, T_SEQ, DIM_, DIM_);
}

// round 11
// speedup vs baseline: 3.6060x; 1.1380x over previous
#include <cuda_runtime.h>
#include <cuda_fp16.h>
#include <math.h>

#define T_SEQ 2048
#define DIM_   1024
#define NH     8
#define HD     128
#define RMS_EPS 1.1920929e-7f
#define C_SC (0.12f * 1.4426950408889634f)   // ATTN_SCALE * log2(e)

// -------------------- scratch (static device globals; no allocs) --------------------
__device__ float  g_qkv  [(size_t)T_SEQ * 3 * DIM_];  // [t][3072] fp32
__device__ __half g_xh   [(size_t)T_SEQ * DIM_];      // fp16 x
__device__ __half g_wqkv [(size_t)3 * DIM_ * DIM_];   // fp16 qkv_w
__device__ __half g_wproj[(size_t)DIM_ * DIM_];       // fp16 c_proj_w
__device__ __half g_qh   [(size_t)NH * T_SEQ * HD];   // [h][t][d]
__device__ __half g_kh   [(size_t)NH * T_SEQ * HD];   // [h][t][d]
__device__ __half g_vt   [(size_t)NH * HD * T_SEQ];   // [h][d][t]
__device__ __half g_yh   [(size_t)T_SEQ * DIM_];      // attention out, fp16
__device__ float  g_rot  [(size_t)T_SEQ * 64];        // [t][2j]=cos, [t][2j+1]=sin, j<32
__device__ float  g_fr   [32];                        // rotary frequencies

// -------------------- helpers --------------------------------------------------------
__device__ __forceinline__ uint2 f4h(float4 v) {
    uint2 r;
    asm("cvt.rn.f16x2.f32 %0, %1, %2;" : "=r"(r.x) : "f"(v.y), "f"(v.x));
    asm("cvt.rn.f16x2.f32 %0, %1, %2;" : "=r"(r.y) : "f"(v.w), "f"(v.z));
    return r;
}
__device__ __forceinline__ unsigned packh2(float lo, float hi) {
    unsigned r;
    asm("cvt.rn.f16x2.f32 %0, %1, %2;" : "=r"(r) : "f"(hi), "f"(lo));
    return r;
}
__device__ __forceinline__ void mma_h(float c[4], const unsigned a[4], const unsigned* b) {
    asm volatile(
        "mma.sync.aligned.m16n8k16.row.col.f32.f16.f16.f32 "
        "{%0,%1,%2,%3}, {%4,%5,%6,%7}, {%8,%9}, {%0,%1,%2,%3};"
        : "+f"(c[0]), "+f"(c[1]), "+f"(c[2]), "+f"(c[3])
        : "r"(a[0]), "r"(a[1]), "r"(a[2]), "r"(a[3]), "r"(b[0]), "r"(b[1]));
}
__device__ __forceinline__ void ldm4(unsigned r[4], unsigned addr) {
    asm volatile("ldmatrix.sync.aligned.m8n8.x4.shared.b16 {%0,%1,%2,%3}, [%4];"
                 : "=r"(r[0]), "=r"(r[1]), "=r"(r[2]), "=r"(r[3]) : "r"(addr));
}
__device__ __forceinline__ unsigned smem_u32(const void* p) {
    unsigned a;
    asm("{.reg .u64 t; cvta.to.shared.u64 t, %1; cvt.u32.u64 %0, t;}" : "=r"(a) : "l"(p));
    return a;
}
__device__ __forceinline__ void cpa16(unsigned dst, const void* src) {
    asm volatile("cp.async.cg.shared.global [%0], [%1], 16;" :: "r"(dst), "l"(src) : "memory");
}
__device__ __forceinline__ void cp_commit() { asm volatile("cp.async.commit_group;" ::: "memory"); }
__device__ __forceinline__ void cp_wait0()  { asm volatile("cp.async.wait_group 0;" ::: "memory"); }
__device__ __forceinline__ void cp_wait1()  { asm volatile("cp.async.wait_group 1;" ::: "memory"); }
__device__ __forceinline__ void cp_wait2()  { asm volatile("cp.async.wait_group 2;" ::: "memory"); }

// -------------------- fused prep: fp32->fp16 x/w_qkv/w_proj + fr table ----------------
// blocks [0,1024): x ; [1024,2560): qkv_w ; [2560,3072): c_proj_w ; 3072: fr
__global__ __launch_bounds__(256)
void prep(const float* __restrict__ x, const float* __restrict__ qkv_w,
          const float* __restrict__ c_proj_w)
{
    const int b = blockIdx.x;
    const float* s;
    __half* d;
    int base;
    if (b < 1024)      { s = x;        d = g_xh;    base = b; }
    else if (b < 2560) { s = qkv_w;    d = g_wqkv;  base = b - 1024; }
    else if (b < 3072) { s = c_proj_w; d = g_wproj; base = b - 2560; }
    else {
        if (threadIdx.x < 32) {
            float tj = (float)threadIdx.x / 31.0f;
            g_fr[threadIdx.x] = (float)exp2(-10.0 * (double)tj);  // bit-identical fr
        }
        return;
    }
    int i = (base * 256 + threadIdx.x) * 8;
    float4 a = *(const float4*)(s + i);
    float4 c = *(const float4*)(s + i + 4);
    uint2 ua = f4h(a), uc = f4h(c);
    *(uint4*)(d + i) = make_uint4(ua.x, ua.y, uc.x, uc.y);
}

// -------------------- rotary table: fp32 Cody-Waite sincos, fr from table ------------
__global__ __launch_bounds__(256)
void rot_build()
{
    int idx = blockIdx.x * 256 + threadIdx.x;   // 0..65535
    int t = idx >> 5, j = idx & 31;
    float th = (float)t * g_fr[j];

    const float C1 = 1.5703125f;
    const float C2 = 4.83826794897e-4f;
    float kf = rintf(th * 0.63661977236758134f);
    int   ki = (int)kf;
    float r  = fmaf(-kf, C1, th);
    r = fmaf(-kf, C2, r);

    float r2 = r * r;
    float sp = fmaf(r2, fmaf(r2, fmaf(r2, 2.75573137e-6f, -1.98412698e-4f),
                             8.33333376e-3f), -1.66666672e-1f);
    sp = fmaf(r * r2, sp, r);
    float cp = fmaf(r2, fmaf(r2, fmaf(r2, fmaf(r2, 2.44331571e-5f, -1.38873162e-3f),
                             4.16666418e-2f), -0.5f), 1.0f);

    float cosv, sinv;
    switch (ki & 3) {
        case 0:  cosv =  cp; sinv =  sp; break;
        case 1:  cosv = -sp; sinv =  cp; break;
        case 2:  cosv = -cp; sinv = -sp; break;
        default: cosv =  sp; sinv = -cp; break;
    }
    g_rot[t * 64 + 2 * j]     = cosv;
    g_rot[t * 64 + 2 * j + 1] = sinv;
}

// -------------------- GEMM (fp16 TC, 2-stage cp.async): C = A @ B^T ------------------
// BM=128, BN=128, BK=64, 256 threads = 8 warps (2m x 4n), warp tile 64x32.
// SMEM rows: 64 halfs + 8 pad = 36 u32. Stage s: A @ s*9216, B @ s*9216+4608.
#define G3_STAGE 9216
#define GEMM_SMEM_BYTES (2 * G3_STAGE * 4)

__global__ __launch_bounds__(256, 2)
void gemm_h3(const __half* __restrict__ A, const __half* __restrict__ B,
             float* __restrict__ C, int M, int N, int K)
{
    extern __shared__ unsigned gsm[];
    const unsigned smb = smem_u32(gsm);
    const int tid  = threadIdx.x;
    const int lane = tid & 31;
    const int wid  = tid >> 5;
    const int wm   = wid >> 2;   // 0..1 -> 64 rows
    const int wn   = wid & 3;    // 0..3 -> 32 cols
    const int m0   = blockIdx.y * 128;
    const int n0   = blockIdx.x * 128;

    const int arow = (lane & 7) + ((lane >> 3) & 1) * 8;
    const int acol = (lane >> 4) * 4;
    const int brow = (lane & 7) + ((lane >> 4) & 1) * 8;
    const int bcol = ((lane >> 3) & 1) * 4;
    const int NK   = K >> 6;

    auto loadAB = [&](int it, int s) {
        const __half* Ab = A + (size_t)m0 * K + it * 64;
        const __half* Bb = B + (size_t)n0 * K + it * 64;
        unsigned da = smb + s * (G3_STAGE * 4);
        unsigned db = da + 4608 * 4;
#pragma unroll
        for (int p = 0; p < 4; p++) {
            int id = tid + p * 256;
            int row = id >> 3, o = id & 7;
            cpa16(da + row * 144u + o * 16u, Ab + (size_t)row * K + o * 8);
        }
#pragma unroll
        for (int p = 0; p < 4; p++) {
            int id = tid + p * 256;
            int row = id >> 3, o = id & 7;
            cpa16(db + row * 144u + o * 16u, Bb + (size_t)row * K + o * 8);
        }
    };

    float acc[4][4][4];
#pragma unroll
    for (int i = 0; i < 4; i++)
#pragma unroll
        for (int j = 0; j < 4; j++)
#pragma unroll
            for (int r = 0; r < 4; r++) acc[i][j][r] = 0.0f;

    loadAB(0, 0); cp_commit();

    for (int it = 0; it < NK; it++) {
        const int s = it & 1;
        if (it + 1 < NK) { loadAB(it + 1, s ^ 1); cp_commit(); cp_wait1(); }
        else             { cp_wait0(); }
        __syncthreads();

        const unsigned ab = smb + s * (G3_STAGE * 4);
        const unsigned bb = ab + 4608 * 4;
#pragma unroll
        for (int ks = 0; ks < 4; ks++) {
            unsigned a[4][4], bq[2][4];
#pragma unroll
            for (int mi = 0; mi < 4; mi++)
                ldm4(a[mi], ab + ((wm * 64 + mi * 16 + arow) * 36 + ks * 8 + acol) * 4);
#pragma unroll
            for (int jp = 0; jp < 2; jp++)
                ldm4(bq[jp], bb + ((wn * 32 + jp * 16 + brow) * 36 + ks * 8 + bcol) * 4);
#pragma unroll
            for (int j = 0; j < 4; j++) {
                const unsigned* pb = &bq[j >> 1][(j & 1) * 2];
#pragma unroll
                for (int mi = 0; mi < 4; mi++)
                    mma_h(acc[mi][j], a[mi], pb);
            }
        }
        __syncthreads();   // all warps done reading stage s before it is reloaded
    }

    const int rq = lane >> 2, cq = lane & 3;
#pragma unroll
    for (int mi = 0; mi < 4; mi++) {
        int r = m0 + wm * 64 + mi * 16 + rq;
#pragma unroll
        for (int j = 0; j < 4; j++) {
            int cn = n0 + wn * 32 + j * 8 + 2 * cq;
            *(float2*)&C[(size_t)r * N + cn]       = make_float2(acc[mi][j][0], acc[mi][j][1]);
            *(float2*)&C[(size_t)(r + 8) * N + cn] = make_float2(acc[mi][j][2], acc[mi][j][3]);
        }
    }
}

// -------------------- q/k transform: one warp per (t,h), no SMEM ---------------------
__global__ __launch_bounds__(256)
void qk_transform()
{
    const int lane = threadIdx.x & 31;
    const int gid  = blockIdx.x * 8 + (threadIdx.x >> 5);
    const int t = gid >> 3;
    const int h = gid & 7;

    const float* base = g_qkv + (size_t)t * (3 * DIM_) + h * HD + lane * 4;
    float4 q4 = *(const float4*)(base);
    float4 k4 = *(const float4*)(base + DIM_);

    float sq = q4.x * q4.x + q4.y * q4.y + q4.z * q4.z + q4.w * q4.w;
    float sk = k4.x * k4.x + k4.y * k4.y + k4.z * k4.z + k4.w * k4.w;
#pragma unroll
    for (int off = 16; off >= 1; off >>= 1) {
        sq += __shfl_xor_sync(0xffffffffu, sq, off);
        sk += __shfl_xor_sync(0xffffffffu, sk, off);
    }
    const float rq = rsqrtf(sq * (1.0f / 128.0f) + RMS_EPS);
    const float rk = rsqrtf(sk * (1.0f / 128.0f) + RMS_EPS);

    float qn[4] = { q4.x * rq, q4.y * rq, q4.z * rq, q4.w * rq };
    float kn[4] = { k4.x * rk, k4.y * rk, k4.z * rk, k4.w * rk };

    float qp[4], kp[4];
#pragma unroll
    for (int i = 0; i < 4; i++) {
        qp[i] = __shfl_xor_sync(0xffffffffu, qn[i], 16);
        kp[i] = __shfl_xor_sync(0xffffffffu, kn[i], 16);
    }

    const int L = lane & 15;
    float cs[4], sn[4];
    if (L < 8) {
        const float* rt = g_rot + t * 64 + L * 8;
        float4 a = *(const float4*)(rt);
        float4 b = *(const float4*)(rt + 4);
        cs[0] = a.x; sn[0] = a.y; cs[1] = a.z; sn[1] = a.w;
        cs[2] = b.x; sn[2] = b.y; cs[3] = b.z; sn[3] = b.w;
    } else {
#pragma unroll
        for (int i = 0; i < 4; i++) { cs[i] = 1.0f; sn[i] = 0.0f; }
    }
    const float sgn = (lane < 16) ? 1.0f : -1.0f;

    float qo[4], ko[4];
#pragma unroll
    for (int i = 0; i < 4; i++) {
        qo[i] = fmaf(sgn * qp[i], sn[i], qn[i] * cs[i]);
        ko[i] = fmaf(sgn * kp[i], sn[i], kn[i] * cs[i]);
    }

    size_t oidx = ((size_t)h * T_SEQ + t) * HD + lane * 4;
    *(uint2*)&g_qh[oidx] = make_uint2(packh2(qo[0], qo[1]), packh2(qo[2], qo[3]));
    *(uint2*)&g_kh[oidx] = make_uint2(packh2(ko[0], ko[1]), packh2(ko[2], ko[3]));
}

// -------------------- v mix + transpose: g_vt[h][d][t] -------------------------------
__global__ __launch_bounds__(128)
void vmix_trans(const float* __restrict__ ve, const float* __restrict__ lambdas)
{
    __shared__ __half tile[64 * 136];
    const int h  = blockIdx.y;
    const int t0 = blockIdx.x * 64;
    const int tid = threadIdx.x;
    const float l0 = lambdas[0], l1 = lambdas[1];

#pragma unroll
    for (int p = 0; p < 16; p++) {
        int f = tid + p * 128;
        int row = f >> 5, c4 = (f & 31) * 4;
        float4 v = *(const float4*)(g_qkv + (size_t)(t0 + row) * (3 * DIM_) + 2 * DIM_ + h * HD + c4);
        float4 e = *(const float4*)(ve + (size_t)(t0 + row) * DIM_ + h * HD + c4);
        tile[row * 136 + c4 + 0] = __float2half_rn(l0 * v.x + l1 * e.x);
        tile[row * 136 + c4 + 1] = __float2half_rn(l0 * v.y + l1 * e.y);
        tile[row * 136 + c4 + 2] = __float2half_rn(l0 * v.z + l1 * e.z);
        tile[row * 136 + c4 + 3] = __float2half_rn(l0 * v.w + l1 * e.w);
    }
    __syncthreads();

#pragma unroll
    for (int p = 0; p < 8; p++) {
        int f = tid + p * 128;
        int d = f >> 3, s8 = (f & 7) * 8;
        __half tmp[8];
#pragma unroll
        for (int i = 0; i < 8; i++) tmp[i] = tile[(s8 + i) * 136 + d];
        *(uint4*)(g_vt + ((size_t)h * HD + d) * T_SEQ + t0 + s8) = *(uint4*)tmp;
    }
}

// -------------------- flash attention: 2 q-tiles/block, 8 warps, 3-buf KV ------------
#define ATT_SMEM_BYTES (35584 * 4)

__global__ __launch_bounds__(256)
void attn_h()
{
    extern __shared__ unsigned sm[];
    const unsigned smb = smem_u32(sm);
    const int tid  = threadIdx.x;
    const int lane = tid & 31;
    const int wg   = tid >> 7;
    const int w    = (tid >> 5) & 3;
    const int rq   = lane >> 2;
    const int cq   = lane & 3;
    const int h    = blockIdx.x & 7;
    const int pr   = blockIdx.x >> 3;
    const int myqt = wg ? (31 - pr) : pr;
    const int qmax = 31 - pr;
    const int q0   = myqt * 64;

    const __half* qh = g_qh + (size_t)h * T_SEQ * HD;
    const __half* kh = g_kh + (size_t)h * T_SEQ * HD;
    const __half* vt = g_vt + (size_t)h * HD * T_SEQ;

    const int arow = (lane & 7) + ((lane >> 3) & 1) * 8;
    const int acol = (lane >> 4) * 4;
    const int brow = (lane & 7) + ((lane >> 4) & 1) * 8;
    const int bcol = ((lane >> 3) & 1) * 4;

    auto loadKV = [&](int t, int s) {
        const int s0 = t * 64;
        const unsigned kb = smb + (8704u + s * 4352u) * 4u;
        const unsigned vb = smb + (21760u + s * 4608u) * 4u;
#pragma unroll
        for (int p = 0; p < 4; p++) {
            int id = tid + p * 256;
            int row = id >> 4, o = id & 15;
            cpa16(kb + row * 272u + o * 16u, kh + (size_t)(s0 + row) * HD + o * 8);
        }
#pragma unroll
        for (int p = 0; p < 4; p++) {
            int id = tid + p * 256;
            int d = id >> 3, o = id & 7;
            cpa16(vb + d * 144u + o * 16u, vt + (size_t)d * T_SEQ + s0 + o * 8);
        }
    };

    {
        int ltid = tid & 127;
#pragma unroll
        for (int p = 0; p < 8; p++) {
            int id = ltid + p * 128;
            int row = id >> 4, o = id & 15;
            cpa16(smb + (wg * 4352u + row * 68u) * 4u + o * 16u,
                  qh + (size_t)(q0 + row) * HD + o * 8);
        }
    }
    cp_commit();
    loadKV(0, 0); cp_commit();
    loadKV(1, 1); cp_commit();

    cp_wait2();
    __syncthreads();

    unsigned qa[8][4];
#pragma unroll
    for (int ks = 0; ks < 8; ks++)
        ldm4(qa[ks], smb + (wg * 4352u + (w * 16 + arow) * 68u + ks * 8 + acol) * 4);

    float m0 = -INFINITY, m1 = -INFINITY, l0 = 0.0f, l1 = 0.0f;
    float O[16][4];
#pragma unroll
    for (int nf = 0; nf < 16; nf++)
#pragma unroll
        for (int r = 0; r < 4; r++) O[nf][r] = 0.0f;

    for (int t = 0; t <= qmax; t++) {
        if (t < qmax) cp_wait1(); else cp_wait0();
        __syncthreads();
        if (t + 2 <= qmax) { loadKV(t + 2, (t + 2) % 3); cp_commit(); }

        if (t <= myqt) {
            const int s = t % 3;
            const unsigned kb = smb + (8704u + s * 4352u) * 4u;
            const unsigned vb = smb + (21760u + s * 4608u) * 4u;

            float sc[8][4];
#pragma unroll
            for (int nf = 0; nf < 8; nf++)
#pragma unroll
                for (int r = 0; r < 4; r++) sc[nf][r] = 0.0f;

#pragma unroll
            for (int ks = 0; ks < 8; ks++) {
#pragma unroll
                for (int np = 0; np < 4; np++) {
                    unsigned kq[4];
                    ldm4(kq, kb + ((np * 16 + brow) * 68u + ks * 8 + bcol) * 4);
                    mma_h(sc[2 * np],     qa[ks], &kq[0]);
                    mma_h(sc[2 * np + 1], qa[ks], &kq[2]);
                }
            }

            const int r0l = w * 16 + rq, r1l = r0l + 8;
#pragma unroll
            for (int nf = 0; nf < 8; nf++) {
                sc[nf][0] *= C_SC; sc[nf][1] *= C_SC;
                sc[nf][2] *= C_SC; sc[nf][3] *= C_SC;
            }
            if (t == myqt) {
#pragma unroll
                for (int nf = 0; nf < 8; nf++) {
                    int c0 = nf * 8 + 2 * cq;
                    if (c0     > r0l) sc[nf][0] = -INFINITY;
                    if (c0 + 1 > r0l) sc[nf][1] = -INFINITY;
                    if (c0     > r1l) sc[nf][2] = -INFINITY;
                    if (c0 + 1 > r1l) sc[nf][3] = -INFINITY;
                }
            }

            float mx0 = -INFINITY, mx1 = -INFINITY;
#pragma unroll
            for (int nf = 0; nf < 8; nf++) {
                mx0 = fmaxf(mx0, fmaxf(sc[nf][0], sc[nf][1]));
                mx1 = fmaxf(mx1, fmaxf(sc[nf][2], sc[nf][3]));
            }
#pragma unroll
            for (int off = 1; off <= 2; off <<= 1) {
                mx0 = fmaxf(mx0, __shfl_xor_sync(0xffffffffu, mx0, off));
                mx1 = fmaxf(mx1, __shfl_xor_sync(0xffffffffu, mx1, off));
            }
            const float nm0 = fmaxf(m0, mx0);
            const float nm1 = fmaxf(m1, mx1);

            float rs0 = 0.0f, rs1 = 0.0f;
            unsigned ph[8][2];
#pragma unroll
            for (int nf = 0; nf < 8; nf++) {
                float p0 = exp2f(sc[nf][0] - nm0);
                float p1 = exp2f(sc[nf][1] - nm0);
                float p2 = exp2f(sc[nf][2] - nm1);
                float p3 = exp2f(sc[nf][3] - nm1);
                rs0 += p0 + p1;
                rs1 += p2 + p3;
                ph[nf][0] = packh2(p0, p1);
                ph[nf][1] = packh2(p2, p3);
            }
#pragma unroll
            for (int off = 1; off <= 2; off <<= 1) {
                rs0 += __shfl_xor_sync(0xffffffffu, rs0, off);
                rs1 += __shfl_xor_sync(0xffffffffu, rs1, off);
            }

            const float al0 = exp2f(m0 - nm0);
            const float al1 = exp2f(m1 - nm1);
            l0 = l0 * al0 + rs0;  m0 = nm0;
            l1 = l1 * al1 + rs1;  m1 = nm1;
#pragma unroll
            for (int nf = 0; nf < 16; nf++) {
                O[nf][0] *= al0; O[nf][1] *= al0;
                O[nf][2] *= al1; O[nf][3] *= al1;
            }

#pragma unroll
            for (int ks = 0; ks < 4; ks++) {
                unsigned a[4] = { ph[2 * ks][0], ph[2 * ks][1],
                                  ph[2 * ks + 1][0], ph[2 * ks + 1][1] };
#pragma unroll
                for (int np = 0; np < 8; np++) {
                    unsigned vq[4];
                    ldm4(vq, vb + ((np * 16 + brow) * 36u + ks * 8 + bcol) * 4);
                    mma_h(O[2 * np],     a, &vq[0]);
                    mma_h(O[2 * np + 1], a, &vq[2]);
                }
            }
        }
    }

    const float inv0 = 1.0f / l0;
    const float inv1 = 1.0f / l1;
    const int row0 = q0 + w * 16 + rq, row1 = row0 + 8;
#pragma unroll
    for (int nf = 0; nf < 16; nf++) {
        int col = h * HD + nf * 8 + 2 * cq;
        *(unsigned*)&g_yh[(size_t)row0 * DIM_ + col] = packh2(O[nf][0] * inv0, O[nf][1] * inv0);
        *(unsigned*)&g_yh[(size_t)row1 * DIM_ + col] = packh2(O[nf][2] * inv1, O[nf][3] * inv1);
    }
}

// -------------------- launch ---------------------------------------------------------
extern "C" void kernel_launch(void* const* d_in, const int* in_sizes, int n_in,
                              void* d_out, int out_size)
{
    const float* x        = (const float*)d_in[0];
    const float* ve       = (const float*)d_in[1];
    const float* qkv_w    = (const float*)d_in[2];
    const float* lambdas  = (const float*)d_in[3];
    const float* c_proj_w = (const float*)d_in[4];
    float* out = (float*)d_out;

    float  *p_qkv;
    __half *p_xh, *p_wqkv, *p_wproj, *p_yh;
    cudaGetSymbolAddress((void**)&p_qkv,   g_qkv);
    cudaGetSymbolAddress((void**)&p_xh,    g_xh);
    cudaGetSymbolAddress((void**)&p_wqkv,  g_wqkv);
    cudaGetSymbolAddress((void**)&p_wproj, g_wproj);
    cudaGetSymbolAddress((void**)&p_yh,    g_yh);

    // 0) fused converts + fr table, then rotary table
    prep<<<3073, 256>>>(x, qkv_w, c_proj_w);
    rot_build<<<256, 256>>>();

    // 1) QKV projection: g_qkv[2048,3072] = xh @ wqkv^T
    cudaFuncSetAttribute(gemm_h3, cudaFuncAttributeMaxDynamicSharedMemorySize, GEMM_SMEM_BYTES);
    gemm_h3<<<dim3(3 * DIM_ / 128, T_SEQ / 128), 256, GEMM_SMEM_BYTES>>>(
        p_xh, p_wqkv, p_qkv, T_SEQ, 3 * DIM_, DIM_);

    // 2) rmsnorm + rotary (warp per (t,h)); v mix + transpose
    qk_transform<<<2048, 256>>>();
    vmix_trans<<<dim3(T_SEQ / 64, NH), 128>>>(ve, lambdas);

    // 3) causal flash attention -> fp16
    cudaFuncSetAttribute(attn_h, cudaFuncAttributeMaxDynamicSharedMemorySize, ATT_SMEM_BYTES);
    attn_h<<<dim3(128), 256, ATT_SMEM_BYTES>>>();

    // 4) output projection: out = yh @ wproj^T
    gemm_h3<<<dim3(DIM_ / 128, T_SEQ / 128), 256, GEMM_SMEM_BYTES>>>(
        p_yh, p_wproj, out, T_SEQ, DIM_, DIM_);
}

// round 14
// speedup vs baseline: 3.6173x; 1.0031x over previous
#include <cuda_runtime.h>
#include <cuda_fp16.h>
#include <math.h>

#define T_SEQ 2048
#define DIM_   1024
#define NH     8
#define HD     128
#define RMS_EPS 1.1920929e-7f
#define C_SC (0.12f * 1.4426950408889634f)   // ATTN_SCALE * log2(e)

// -------------------- scratch (static device globals; no allocs) --------------------
__device__ __half g_xh   [(size_t)T_SEQ * DIM_];      // fp16 x
__device__ __half g_wqkv [(size_t)3 * DIM_ * DIM_];   // fp16 qkv_w
__device__ __half g_wproj[(size_t)DIM_ * DIM_];       // fp16 c_proj_w
__device__ __half g_qh   [(size_t)NH * T_SEQ * HD];   // [h][t][d]
__device__ __half g_kh   [(size_t)NH * T_SEQ * HD];   // [h][t][d]
__device__ __half g_vt   [(size_t)NH * HD * T_SEQ];   // [h][d][t]
__device__ __half g_yh   [(size_t)T_SEQ * DIM_];      // attention out, fp16
__device__ float  g_rot  [(size_t)T_SEQ * 64];        // [t][2j]=cos, [t][2j+1]=sin, j<32
__device__ float  g_fr   [32];                        // rotary frequencies

// -------------------- helpers --------------------------------------------------------
__device__ __forceinline__ uint2 f4h(float4 v) {
    uint2 r;
    asm("cvt.rn.f16x2.f32 %0, %1, %2;" : "=r"(r.x) : "f"(v.y), "f"(v.x));
    asm("cvt.rn.f16x2.f32 %0, %1, %2;" : "=r"(r.y) : "f"(v.w), "f"(v.z));
    return r;
}
__device__ __forceinline__ unsigned packh2(float lo, float hi) {
    unsigned r;
    asm("cvt.rn.f16x2.f32 %0, %1, %2;" : "=r"(r) : "f"(hi), "f"(lo));
    return r;
}
__device__ __forceinline__ void mma_h(float c[4], const unsigned a[4], const unsigned* b) {
    asm volatile(
        "mma.sync.aligned.m16n8k16.row.col.f32.f16.f16.f32 "
        "{%0,%1,%2,%3}, {%4,%5,%6,%7}, {%8,%9}, {%0,%1,%2,%3};"
        : "+f"(c[0]), "+f"(c[1]), "+f"(c[2]), "+f"(c[3])
        : "r"(a[0]), "r"(a[1]), "r"(a[2]), "r"(a[3]), "r"(b[0]), "r"(b[1]));
}
__device__ __forceinline__ void ldm4(unsigned r[4], unsigned addr) {
    asm volatile("ldmatrix.sync.aligned.m8n8.x4.shared.b16 {%0,%1,%2,%3}, [%4];"
                 : "=r"(r[0]), "=r"(r[1]), "=r"(r[2]), "=r"(r[3]) : "r"(addr));
}
__device__ __forceinline__ unsigned smem_u32(const void* p) {
    unsigned a;
    asm("{.reg .u64 t; cvta.to.shared.u64 t, %1; cvt.u32.u64 %0, t;}" : "=r"(a) : "l"(p));
    return a;
}
__device__ __forceinline__ void cpa16(unsigned dst, const void* src) {
    asm volatile("cp.async.cg.shared.global [%0], [%1], 16;" :: "r"(dst), "l"(src) : "memory");
}
__device__ __forceinline__ void cp_commit() { asm volatile("cp.async.commit_group;" ::: "memory"); }
__device__ __forceinline__ void cp_wait0()  { asm volatile("cp.async.wait_group 0;" ::: "memory"); }
__device__ __forceinline__ void cp_wait1()  { asm volatile("cp.async.wait_group 1;" ::: "memory"); }
__device__ __forceinline__ void cp_wait2()  { asm volatile("cp.async.wait_group 2;" ::: "memory"); }

// -------------------- fused prep: fp32->fp16 x/w_qkv/w_proj + fr table ----------------
__global__ __launch_bounds__(256)
void prep(const float* __restrict__ x, const float* __restrict__ qkv_w,
          const float* __restrict__ c_proj_w)
{
    const int b = blockIdx.x;
    const float* s;
    __half* d;
    int base;
    if (b < 1024)      { s = x;        d = g_xh;    base = b; }
    else if (b < 2560) { s = qkv_w;    d = g_wqkv;  base = b - 1024; }
    else if (b < 3072) { s = c_proj_w; d = g_wproj; base = b - 2560; }
    else {
        if (threadIdx.x < 32) {
            float tj = (float)threadIdx.x / 31.0f;
            g_fr[threadIdx.x] = (float)exp2(-10.0 * (double)tj);  // bit-identical fr
        }
        return;
    }
    int i = (base * 256 + threadIdx.x) * 8;
    float4 a = *(const float4*)(s + i);
    float4 c = *(const float4*)(s + i + 4);
    uint2 ua = f4h(a), uc = f4h(c);
    *(uint4*)(d + i) = make_uint4(ua.x, ua.y, uc.x, uc.y);
}

// -------------------- rotary table: fp32 Cody-Waite sincos ---------------------------
__global__ __launch_bounds__(256)
void rot_build()
{
    int idx = blockIdx.x * 256 + threadIdx.x;
    int t = idx >> 5, j = idx & 31;
    float th = (float)t * g_fr[j];

    const float C1 = 1.5703125f;
    const float C2 = 4.83826794897e-4f;
    float kf = rintf(th * 0.63661977236758134f);
    int   ki = (int)kf;
    float r  = fmaf(-kf, C1, th);
    r = fmaf(-kf, C2, r);

    float r2 = r * r;
    float sp = fmaf(r2, fmaf(r2, fmaf(r2, 2.75573137e-6f, -1.98412698e-4f),
                             8.33333376e-3f), -1.66666672e-1f);
    sp = fmaf(r * r2, sp, r);
    float cp = fmaf(r2, fmaf(r2, fmaf(r2, fmaf(r2, 2.44331571e-5f, -1.38873162e-3f),
                             4.16666418e-2f), -0.5f), 1.0f);

    float cosv, sinv;
    switch (ki & 3) {
        case 0:  cosv =  cp; sinv =  sp; break;
        case 1:  cosv = -sp; sinv =  cp; break;
        case 2:  cosv = -cp; sinv = -sp; break;
        default: cosv =  sp; sinv = -cp; break;
    }
    g_rot[t * 64 + 2 * j]     = cosv;
    g_rot[t * 64 + 2 * j + 1] = sinv;
}

// -------------------- fused QKV GEMM + rmsnorm/rotary/vmix epilogue ------------------
// BM=128, BN=128, BK=64. Grid (24,16): bx -> type = bx>>3 (0=q,1=k,2=v), head = bx&7.
// Epilogue smem reuse: stage fp32 [128][132] + red [4][128] (q/k); half tile [128][136] (v).
#define G3_STAGE 9216
#define GEMM_SMEM_BYTES (2 * G3_STAGE * 4)

__global__ __launch_bounds__(256, 2)
void gemm_qkv(const __half* __restrict__ A, const __half* __restrict__ B,
              const float* __restrict__ ve, const float* __restrict__ lambdas)
{
    extern __shared__ unsigned gsm[];
    const unsigned smb = smem_u32(gsm);
    const int tid  = threadIdx.x;
    const int lane = tid & 31;
    const int wid  = tid >> 5;
    const int wm   = wid >> 2;
    const int wn   = wid & 3;
    const int m0   = blockIdx.y * 128;
    const int n0   = blockIdx.x * 128;
    const int type = blockIdx.x >> 3;
    const int head = blockIdx.x & 7;
    const int K    = DIM_;
    const int rq   = lane >> 2, cq = lane & 3;

    const int arow = (lane & 7) + ((lane >> 3) & 1) * 8;
    const int acol = (lane >> 4) * 4;
    const int brow = (lane & 7) + ((lane >> 4) & 1) * 8;
    const int bcol = ((lane >> 3) & 1) * 4;
    const int NK   = K >> 6;

    auto loadAB = [&](int it, int s) {
        const __half* Ab = A + (size_t)m0 * K + it * 64;
        const __half* Bb = B + (size_t)n0 * K + it * 64;
        unsigned da = smb + s * (G3_STAGE * 4);
        unsigned db = da + 4608 * 4;
#pragma unroll
        for (int p = 0; p < 4; p++) {
            int id = tid + p * 256;
            int row = id >> 3, o = id & 7;
            cpa16(da + row * 144u + o * 16u, Ab + (size_t)row * K + o * 8);
        }
#pragma unroll
        for (int p = 0; p < 4; p++) {
            int id = tid + p * 256;
            int row = id >> 3, o = id & 7;
            cpa16(db + row * 144u + o * 16u, Bb + (size_t)row * K + o * 8);
        }
    };

    float acc[4][4][4];
#pragma unroll
    for (int i = 0; i < 4; i++)
#pragma unroll
        for (int j = 0; j < 4; j++)
#pragma unroll
            for (int r = 0; r < 4; r++) acc[i][j][r] = 0.0f;

    loadAB(0, 0); cp_commit();

    for (int it = 0; it < NK; it++) {
        const int s = it & 1;
        if (it + 1 < NK) { loadAB(it + 1, s ^ 1); cp_commit(); cp_wait1(); }
        else             { cp_wait0(); }
        __syncthreads();

        const unsigned ab = smb + s * (G3_STAGE * 4);
        const unsigned bb = ab + 4608 * 4;
#pragma unroll
        for (int ks = 0; ks < 4; ks++) {
            unsigned a[4][4], bq[2][4];
#pragma unroll
            for (int mi = 0; mi < 4; mi++)
                ldm4(a[mi], ab + ((wm * 64 + mi * 16 + arow) * 36 + ks * 8 + acol) * 4);
#pragma unroll
            for (int jp = 0; jp < 2; jp++)
                ldm4(bq[jp], bb + ((wn * 32 + jp * 16 + brow) * 36 + ks * 8 + bcol) * 4);
#pragma unroll
            for (int j = 0; j < 4; j++) {
                const unsigned* pb = &bq[j >> 1][(j & 1) * 2];
#pragma unroll
                for (int mi = 0; mi < 4; mi++)
                    mma_h(acc[mi][j], a[mi], pb);
            }
        }
        __syncthreads();
    }

    // ---------------- fused epilogue ----------------
    if (type < 2) {
        // q/k: rmsnorm + rotary -> fp16 [h][t][d]
        float* stageF = (float*)gsm;                 // [128][132]
        float* red    = (float*)gsm + 16896;         // [4][128]

        // per-row sum of squares: thread partial over its 8 cols, quad-shuffle over cq
#pragma unroll
        for (int mi = 0; mi < 4; mi++) {
            float p0 = 0.0f, p1 = 0.0f;
#pragma unroll
            for (int j = 0; j < 4; j++) {
                p0 = fmaf(acc[mi][j][0], acc[mi][j][0], p0);
                p0 = fmaf(acc[mi][j][1], acc[mi][j][1], p0);
                p1 = fmaf(acc[mi][j][2], acc[mi][j][2], p1);
                p1 = fmaf(acc[mi][j][3], acc[mi][j][3], p1);
            }
            p0 += __shfl_xor_sync(0xffffffffu, p0, 1);
            p0 += __shfl_xor_sync(0xffffffffu, p0, 2);
            p1 += __shfl_xor_sync(0xffffffffu, p1, 1);
            p1 += __shfl_xor_sync(0xffffffffu, p1, 2);
            if (cq == 0) {
                int row = wm * 64 + mi * 16 + rq;
                red[wn * 128 + row]     = p0;
                red[wn * 128 + row + 8] = p1;
            }
        }
        __syncthreads();

        // normalize accumulators in registers
#pragma unroll
        for (int mi = 0; mi < 4; mi++) {
            int row0 = wm * 64 + mi * 16 + rq;
            float s0 = red[row0] + red[128 + row0] + red[256 + row0] + red[384 + row0];
            float s1 = red[row0 + 8] + red[128 + row0 + 8] + red[256 + row0 + 8] + red[384 + row0 + 8];
            float rn0 = rsqrtf(s0 * (1.0f / 128.0f) + RMS_EPS);
            float rn1 = rsqrtf(s1 * (1.0f / 128.0f) + RMS_EPS);
#pragma unroll
            for (int j = 0; j < 4; j++) {
                acc[mi][j][0] *= rn0; acc[mi][j][1] *= rn0;
                acc[mi][j][2] *= rn1; acc[mi][j][3] *= rn1;
            }
        }
        __syncthreads();   // red reads done before stage overwrites smem

        // stage normalized values for rotary pairing
#pragma unroll
        for (int mi = 0; mi < 4; mi++) {
            int row0 = wm * 64 + mi * 16 + rq, row1 = row0 + 8;
            int c = wn * 32 + 2 * cq;
#pragma unroll
            for (int j = 0; j < 4; j++) {
                *(float2*)&stageF[row0 * 132 + c + j * 8] = make_float2(acc[mi][j][0], acc[mi][j][1]);
                *(float2*)&stageF[row1 * 132 + c + j * 8] = make_float2(acc[mi][j][2], acc[mi][j][3]);
            }
        }
        __syncthreads();

        __half* dst = (type == 0 ? g_qh : g_kh) + (size_t)head * T_SEQ * HD;
        const bool dorot = ((wn & 1) == 0);          // wn 0,2 need table; wn 1,3 passthrough
        const float sgn = (wn == 0) ? 1.0f : -1.0f;
#pragma unroll
        for (int mi = 0; mi < 4; mi++) {
#pragma unroll
            for (int p = 0; p < 2; p++) {
                int row_l = wm * 64 + mi * 16 + rq + p * 8;
                int row_g = m0 + row_l;
#pragma unroll
                for (int j = 0; j < 4; j++) {
                    int c = wn * 32 + j * 8 + 2 * cq;
                    float v0 = acc[mi][j][2 * p], v1 = acc[mi][j][2 * p + 1];
                    float o0 = v0, o1 = v1;
                    if (dorot) {
                        float2 pp = *(float2*)&stageF[row_l * 132 + (c ^ 64)];
                        float4 cs = *(const float4*)&g_rot[(size_t)row_g * 64 + 2 * (c & 63)];
                        o0 = fmaf(sgn * pp.x, cs.y, v0 * cs.x);
                        o1 = fmaf(sgn * pp.y, cs.w, v1 * cs.z);
                    }
                    *(unsigned*)&dst[(size_t)row_g * HD + c] = packh2(o0, o1);
                }
            }
        }
    } else {
        // v: lambda mix with ve, transpose -> g_vt[h][d][t]
        const float l0v = lambdas[0], l1v = lambdas[1];
        __half* tile = (__half*)gsm;                 // [128][136]
#pragma unroll
        for (int mi = 0; mi < 4; mi++) {
            int row0 = wm * 64 + mi * 16 + rq, row1 = row0 + 8;
#pragma unroll
            for (int j = 0; j < 4; j++) {
                int c = wn * 32 + j * 8 + 2 * cq;
                float2 e0 = *(const float2*)&ve[(size_t)(m0 + row0) * DIM_ + head * HD + c];
                float2 e1 = *(const float2*)&ve[(size_t)(m0 + row1) * DIM_ + head * HD + c];
                *(unsigned*)&tile[row0 * 136 + c] =
                    packh2(fmaf(l1v, e0.x, l0v * acc[mi][j][0]), fmaf(l1v, e0.y, l0v * acc[mi][j][1]));
                *(unsigned*)&tile[row1 * 136 + c] =
                    packh2(fmaf(l1v, e1.x, l0v * acc[mi][j][2]), fmaf(l1v, e1.y, l0v * acc[mi][j][3]));
            }
        }
        __syncthreads();
#pragma unroll
        for (int p = 0; p < 8; p++) {
            int id = tid + p * 256;
            int d = id >> 4, t8 = (id & 15) * 8;
            __half tmp[8];
#pragma unroll
            for (int i = 0; i < 8; i++) tmp[i] = tile[(t8 + i) * 136 + d];
            *(uint4*)&g_vt[((size_t)head * HD + d) * T_SEQ + m0 + t8] = *(uint4*)tmp;
        }
    }
}

// -------------------- plain GEMM (fp16 TC, 2-stage): C = A @ B^T (proj) --------------
__global__ __launch_bounds__(256, 2)
void gemm_h3(const __half* __restrict__ A, const __half* __restrict__ B,
             float* __restrict__ C, int M, int N, int K)
{
    extern __shared__ unsigned gsm[];
    const unsigned smb = smem_u32(gsm);
    const int tid  = threadIdx.x;
    const int lane = tid & 31;
    const int wid  = tid >> 5;
    const int wm   = wid >> 2;
    const int wn   = wid & 3;
    const int m0   = blockIdx.y * 128;
    const int n0   = blockIdx.x * 128;

    const int arow = (lane & 7) + ((lane >> 3) & 1) * 8;
    const int acol = (lane >> 4) * 4;
    const int brow = (lane & 7) + ((lane >> 4) & 1) * 8;
    const int bcol = ((lane >> 3) & 1) * 4;
    const int NK   = K >> 6;

    auto loadAB = [&](int it, int s) {
        const __half* Ab = A + (size_t)m0 * K + it * 64;
        const __half* Bb = B + (size_t)n0 * K + it * 64;
        unsigned da = smb + s * (G3_STAGE * 4);
        unsigned db = da + 4608 * 4;
#pragma unroll
        for (int p = 0; p < 4; p++) {
            int id = tid + p * 256;
            int row = id >> 3, o = id & 7;
            cpa16(da + row * 144u + o * 16u, Ab + (size_t)row * K + o * 8);
        }
#pragma unroll
        for (int p = 0; p < 4; p++) {
            int id = tid + p * 256;
            int row = id >> 3, o = id & 7;
            cpa16(db + row * 144u + o * 16u, Bb + (size_t)row * K + o * 8);
        }
    };

    float acc[4][4][4];
#pragma unroll
    for (int i = 0; i < 4; i++)
#pragma unroll
        for (int j = 0; j < 4; j++)
#pragma unroll
            for (int r = 0; r < 4; r++) acc[i][j][r] = 0.0f;

    loadAB(0, 0); cp_commit();

    for (int it = 0; it < NK; it++) {
        const int s = it & 1;
        if (it + 1 < NK) { loadAB(it + 1, s ^ 1); cp_commit(); cp_wait1(); }
        else             { cp_wait0(); }
        __syncthreads();

        const unsigned ab = smb + s * (G3_STAGE * 4);
        const unsigned bb = ab + 4608 * 4;
#pragma unroll
        for (int ks = 0; ks < 4; ks++) {
            unsigned a[4][4], bq[2][4];
#pragma unroll
            for (int mi = 0; mi < 4; mi++)
                ldm4(a[mi], ab + ((wm * 64 + mi * 16 + arow) * 36 + ks * 8 + acol) * 4);
#pragma unroll
            for (int jp = 0; jp < 2; jp++)
                ldm4(bq[jp], bb + ((wn * 32 + jp * 16 + brow) * 36 + ks * 8 + bcol) * 4);
#pragma unroll
            for (int j = 0; j < 4; j++) {
                const unsigned* pb = &bq[j >> 1][(j & 1) * 2];
#pragma unroll
                for (int mi = 0; mi < 4; mi++)
                    mma_h(acc[mi][j], a[mi], pb);
            }
        }
        __syncthreads();
    }

    const int rq = lane >> 2, cq = lane & 3;
#pragma unroll
    for (int mi = 0; mi < 4; mi++) {
        int r = m0 + wm * 64 + mi * 16 + rq;
#pragma unroll
        for (int j = 0; j < 4; j++) {
            int cn = n0 + wn * 32 + j * 8 + 2 * cq;
            *(float2*)&C[(size_t)r * N + cn]       = make_float2(acc[mi][j][0], acc[mi][j][1]);
            *(float2*)&C[(size_t)(r + 8) * N + cn] = make_float2(acc[mi][j][2], acc[mi][j][3]);
        }
    }
}

// -------------------- flash attention: 2 q-tiles/block, 8 warps, 3-buf KV ------------
#define ATT_SMEM_BYTES (35584 * 4)

__global__ __launch_bounds__(256)
void attn_h()
{
    extern __shared__ unsigned sm[];
    const unsigned smb = smem_u32(sm);
    const int tid  = threadIdx.x;
    const int lane = tid & 31;
    const int wg   = tid >> 7;
    const int w    = (tid >> 5) & 3;
    const int rq   = lane >> 2;
    const int cq   = lane & 3;
    const int h    = blockIdx.x & 7;
    const int pr   = blockIdx.x >> 3;
    const int myqt = wg ? (31 - pr) : pr;
    const int qmax = 31 - pr;
    const int q0   = myqt * 64;

    const __half* qh = g_qh + (size_t)h * T_SEQ * HD;
    const __half* kh = g_kh + (size_t)h * T_SEQ * HD;
    const __half* vt = g_vt + (size_t)h * HD * T_SEQ;

    const int arow = (lane & 7) + ((lane >> 3) & 1) * 8;
    const int acol = (lane >> 4) * 4;
    const int brow = (lane & 7) + ((lane >> 4) & 1) * 8;
    const int bcol = ((lane >> 3) & 1) * 4;

    auto loadKV = [&](int t, int s) {
        const int s0 = t * 64;
        const unsigned kb = smb + (8704u + s * 4352u) * 4u;
        const unsigned vb = smb + (21760u + s * 4608u) * 4u;
#pragma unroll
        for (int p = 0; p < 4; p++) {
            int id = tid + p * 256;
            int row = id >> 4, o = id & 15;
            cpa16(kb + row * 272u + o * 16u, kh + (size_t)(s0 + row) * HD + o * 8);
        }
#pragma unroll
        for (int p = 0; p < 4; p++) {
            int id = tid + p * 256;
            int d = id >> 3, o = id & 7;
            cpa16(vb + d * 144u + o * 16u, vt + (size_t)d * T_SEQ + s0 + o * 8);
        }
    };

    {
        int ltid = tid & 127;
#pragma unroll
        for (int p = 0; p < 8; p++) {
            int id = ltid + p * 128;
            int row = id >> 4, o = id & 15;
            cpa16(smb + (wg * 4352u + row * 68u) * 4u + o * 16u,
                  qh + (size_t)(q0 + row) * HD + o * 8);
        }
    }
    cp_commit();
    loadKV(0, 0); cp_commit();
    loadKV(1, 1); cp_commit();

    cp_wait2();
    __syncthreads();

    unsigned qa[8][4];
#pragma unroll
    for (int ks = 0; ks < 8; ks++)
        ldm4(qa[ks], smb + (wg * 4352u + (w * 16 + arow) * 68u + ks * 8 + acol) * 4);

    float m0 = -INFINITY, m1 = -INFINITY, l0 = 0.0f, l1 = 0.0f;
    float O[16][4];
#pragma unroll
    for (int nf = 0; nf < 16; nf++)
#pragma unroll
        for (int r = 0; r < 4; r++) O[nf][r] = 0.0f;

    for (int t = 0; t <= qmax; t++) {
        if (t < qmax) cp_wait1(); else cp_wait0();
        __syncthreads();
        if (t + 2 <= qmax) { loadKV(t + 2, (t + 2) % 3); cp_commit(); }

        if (t <= myqt) {
            const int s = t % 3;
            const unsigned kb = smb + (8704u + s * 4352u) * 4u;
            const unsigned vb = smb + (21760u + s * 4608u) * 4u;

            float sc[8][4];
#pragma unroll
            for (int nf = 0; nf < 8; nf++)
#pragma unroll
                for (int r = 0; r < 4; r++) sc[nf][r] = 0.0f;

#pragma unroll
            for (int ks = 0; ks < 8; ks++) {
#pragma unroll
                for (int np = 0; np < 4; np++) {
                    unsigned kq[4];
                    ldm4(kq, kb + ((np * 16 + brow) * 68u + ks * 8 + bcol) * 4);
                    mma_h(sc[2 * np],     qa[ks], &kq[0]);
                    mma_h(sc[2 * np + 1], qa[ks], &kq[2]);
                }
            }

            const int r0l = w * 16 + rq, r1l = r0l + 8;
#pragma unroll
            for (int nf = 0; nf < 8; nf++) {
                sc[nf][0] *= C_SC; sc[nf][1] *= C_SC;
                sc[nf][2] *= C_SC; sc[nf][3] *= C_SC;
            }
            if (t == myqt) {
#pragma unroll
                for (int nf = 0; nf < 8; nf++) {
                    int c0 = nf * 8 + 2 * cq;
                    if (c0     > r0l) sc[nf][0] = -INFINITY;
                    if (c0 + 1 > r0l) sc[nf][1] = -INFINITY;
                    if (c0     > r1l) sc[nf][2] = -INFINITY;
                    if (c0 + 1 > r1l) sc[nf][3] = -INFINITY;
                }
            }

            float mx0 = -INFINITY, mx1 = -INFINITY;
#pragma unroll
            for (int nf = 0; nf < 8; nf++) {
                mx0 = fmaxf(mx0, fmaxf(sc[nf][0], sc[nf][1]));
                mx1 = fmaxf(mx1, fmaxf(sc[nf][2], sc[nf][3]));
            }
#pragma unroll
            for (int off = 1; off <= 2; off <<= 1) {
                mx0 = fmaxf(mx0, __shfl_xor_sync(0xffffffffu, mx0, off));
                mx1 = fmaxf(mx1, __shfl_xor_sync(0xffffffffu, mx1, off));
            }
            const float nm0 = fmaxf(m0, mx0);
            const float nm1 = fmaxf(m1, mx1);

            float rs0 = 0.0f, rs1 = 0.0f;
            unsigned ph[8][2];
#pragma unroll
            for (int nf = 0; nf < 8; nf++) {
                float p0 = exp2f(sc[nf][0] - nm0);
                float p1 = exp2f(sc[nf][1] - nm0);
                float p2 = exp2f(sc[nf][2] - nm1);
                float p3 = exp2f(sc[nf][3] - nm1);
                rs0 += p0 + p1;
                rs1 += p2 + p3;
                ph[nf][0] = packh2(p0, p1);
                ph[nf][1] = packh2(p2, p3);
            }
#pragma unroll
            for (int off = 1; off <= 2; off <<= 1) {
                rs0 += __shfl_xor_sync(0xffffffffu, rs0, off);
                rs1 += __shfl_xor_sync(0xffffffffu, rs1, off);
            }

            const float al0 = exp2f(m0 - nm0);
            const float al1 = exp2f(m1 - nm1);
            l0 = l0 * al0 + rs0;  m0 = nm0;
            l1 = l1 * al1 + rs1;  m1 = nm1;
#pragma unroll
            for (int nf = 0; nf < 16; nf++) {
                O[nf][0] *= al0; O[nf][1] *= al0;
                O[nf][2] *= al1; O[nf][3] *= al1;
            }

#pragma unroll
            for (int ks = 0; ks < 4; ks++) {
                unsigned a[4] = { ph[2 * ks][0], ph[2 * ks][1],
                                  ph[2 * ks + 1][0], ph[2 * ks + 1][1] };
#pragma unroll
                for (int np = 0; np < 8; np++) {
                    unsigned vq[4];
                    ldm4(vq, vb + ((np * 16 + brow) * 36u + ks * 8 + bcol) * 4);
                    mma_h(O[2 * np],     a, &vq[0]);
                    mma_h(O[2 * np + 1], a, &vq[2]);
                }
            }
        }
    }

    const float inv0 = 1.0f / l0;
    const float inv1 = 1.0f / l1;
    const int row0 = q0 + w * 16 + rq, row1 = row0 + 8;
#pragma unroll
    for (int nf = 0; nf < 16; nf++) {
        int col = h * HD + nf * 8 + 2 * cq;
        *(unsigned*)&g_yh[(size_t)row0 * DIM_ + col] = packh2(O[nf][0] * inv0, O[nf][1] * inv0);
        *(unsigned*)&g_yh[(size_t)row1 * DIM_ + col] = packh2(O[nf][2] * inv1, O[nf][3] * inv1);
    }
}

// -------------------- launch ---------------------------------------------------------
extern "C" void kernel_launch(void* const* d_in, const int* in_sizes, int n_in,
                              void* d_out, int out_size)
{
    const float* x        = (const float*)d_in[0];
    const float* ve       = (const float*)d_in[1];
    const float* qkv_w    = (const float*)d_in[2];
    const float* lambdas  = (const float*)d_in[3];
    const float* c_proj_w = (const float*)d_in[4];
    float* out = (float*)d_out;

    __half *p_xh, *p_wqkv, *p_wproj, *p_yh;
    cudaGetSymbolAddress((void**)&p_xh,    g_xh);
    cudaGetSymbolAddress((void**)&p_wqkv,  g_wqkv);
    cudaGetSymbolAddress((void**)&p_wproj, g_wproj);
    cudaGetSymbolAddress((void**)&p_yh,    g_yh);

    // 0) fused converts + fr table, then rotary table
    prep<<<3073, 256>>>(x, qkv_w, c_proj_w);
    rot_build<<<256, 256>>>();

    // 1) QKV projection with fused rmsnorm/rotary/vmix epilogue -> g_qh/g_kh/g_vt
    cudaFuncSetAttribute(gemm_qkv, cudaFuncAttributeMaxDynamicSharedMemorySize, GEMM_SMEM_BYTES);
    gemm_qkv<<<dim3(24, T_SEQ / 128), 256, GEMM_SMEM_BYTES>>>(p_xh, p_wqkv, ve, lambdas);

    // 2) causal flash attention -> fp16 g_yh
    cudaFuncSetAttribute(attn_h, cudaFuncAttributeMaxDynamicSharedMemorySize, ATT_SMEM_BYTES);
    attn_h<<<dim3(128), 256, ATT_SMEM_BYTES>>>();

    // 3) output projection: out = yh @ wproj^T
    cudaFuncSetAttribute(gemm_h3, cudaFuncAttributeMaxDynamicSharedMemorySize, GEMM_SMEM_BYTES);
    gemm_h3<<<dim3(DIM_ / 128, T_SEQ / 128), 256, GEMM_SMEM_BYTES>>>(
        p_yh, p_wproj, out, T_SEQ, DIM_, DIM_);
}